// round 8
// baseline (speedup 1.0000x reference)
#include <cuda_runtime.h>
#include <cuda_fp16.h>
#include <cstdint>

#define N_ROWS 8192
#define DIM    512
#define BT     64            // 8192/128 tiles per dimension
#define MARGIN 0.35f
#define KC     128           // K int8 elems per smem chunk (128B rows)
#define NCH    (DIM / KC)    // 4
#define TILEB  (128 * KC)           // 16384 per operand tile (int8)
#define STAGEB (2 * TILEB)          // A + B = 32768
#define NSTAGE 3
#define SMEMDYN (NSTAGE * STAGEB)   // 98304
#define NTILES ((BT * (BT + 1)) / 2)

// ---------------- scratch (device globals; no allocation allowed) ----------
__device__ __align__(16) signed char g_q[N_ROWS * DIM];
__device__ float    g_sc[N_ROWS];    // per-row quant scale
__device__ float    g_sq[N_ROWS];
__device__ float    g_ce[N_ROWS];
__device__ unsigned g_pos[N_ROWS];
__device__ unsigned g_neg[N_ROWS];
__device__ int      g_lab[N_ROWS];
__device__ unsigned g_done;          // zero-init; finalizer re-zeros for graph replay

// ---------------- float <-> monotone unsigned encoding ---------------------
__device__ __forceinline__ unsigned f2ord(float f) {
    unsigned u = __float_as_uint(f);
    return (u & 0x80000000u) ? ~u : (u | 0x80000000u);
}
__device__ __forceinline__ float ord2f(unsigned u) {
    unsigned b = (u & 0x80000000u) ? (u ^ 0x80000000u) : ~u;
    return __uint_as_float(b);
}
__device__ __forceinline__ float dev_inf() { return __int_as_float(0x7f800000); }

// ---------------- mbarrier helpers ------------------------------------------
#define MBAR_INIT(a, c) \
    asm volatile("mbarrier.init.shared.b64 [%0], %1;" :: "r"((uint32_t)(a)), "r"((uint32_t)(c)) : "memory")
#define MBAR_ARRIVE(a) \
    asm volatile("mbarrier.arrive.shared.b64 _, [%0];" :: "r"((uint32_t)(a)) : "memory")
#define CP_MBAR_ARRIVE(a) \
    asm volatile("cp.async.mbarrier.arrive.noinc.shared.b64 [%0];" :: "r"((uint32_t)(a)) : "memory")
#define MBAR_WAIT(a, ph) do {                                                          \
    uint32_t _m = (uint32_t)(a), _p = (uint32_t)(ph), _d;                              \
    asm volatile("{ .reg .pred p; mbarrier.try_wait.parity.acquire.cta.shared::cta.b64 p, [%1], %2;" \
                 " selp.b32 %0, 1, 0, p; }" : "=r"(_d) : "r"(_m), "r"(_p) : "memory"); \
    if (!_d) {                                                                         \
        asm volatile("{ .reg .pred P1; WL_%=: mbarrier.try_wait.parity.acquire.cta.shared::cta.b64 P1, [%0], %1, 0x989680;" \
                     " @P1 bra.uni WD_%=; bra.uni WL_%=; WD_%=: }" :: "r"(_m), "r"(_p) : "memory"); \
    } } while (0)

// ---------------- prep: norms, CE, int8 quantize, label detect, init --------
__global__ void prep_kernel(const float* __restrict__ x, const void* __restrict__ labraw) {
    int row = blockIdx.x;
    int t   = threadIdx.x;          // 128 threads
    const float* xr = x + (size_t)row * DIM;

    // int64 labels in [0,512) -> every odd 32-bit word is zero (per-block vote).
    const int* raw32 = (const int*)labraw;
    int lab64 = !__syncthreads_or(raw32[2 * t + 1] != 0);

    float v[4];
#pragma unroll
    for (int i = 0; i < 4; i++) v[i] = xr[t + 128 * i];

    float ss = 0.f, mx = -dev_inf(), ma = 0.f;
#pragma unroll
    for (int i = 0; i < 4; i++) {
        ss += v[i] * v[i];
        mx = fmaxf(mx, v[i]);
        ma = fmaxf(ma, fabsf(v[i]));
    }
#pragma unroll
    for (int o = 16; o; o >>= 1) {
        ss += __shfl_xor_sync(0xffffffffu, ss, o);
        mx  = fmaxf(mx, __shfl_xor_sync(0xffffffffu, mx, o));
        ma  = fmaxf(ma, __shfl_xor_sync(0xffffffffu, ma, o));
    }
    __shared__ float s_ss[4], s_mx[4], s_ma[4], s_sq[4], s_se[4];
    int w = t >> 5, l = t & 31;
    if (l == 0) { s_ss[w] = ss; s_mx[w] = mx; s_ma[w] = ma; }
    __syncthreads();
    ss = s_ss[0] + s_ss[1] + s_ss[2] + s_ss[3];
    mx = fmaxf(fmaxf(s_mx[0], s_mx[1]), fmaxf(s_mx[2], s_mx[3]));
    ma = fmaxf(fmaxf(s_ma[0], s_ma[1]), fmaxf(s_ma[2], s_ma[3]));

    float norm = sqrtf(ss);
    float qinv = 127.0f / ma;
    float sq = 0.f, se = 0.f;
#pragma unroll
    for (int i = 0; i < 4; i++) {
        float xn = v[i] / norm;
        sq += xn * xn;
        se += expf(v[i] - mx);
    }
#pragma unroll
    for (int o = 16; o; o >>= 1) {
        sq += __shfl_xor_sync(0xffffffffu, sq, o);
        se += __shfl_xor_sync(0xffffffffu, se, o);
    }
    if (l == 0) { s_sq[w] = sq; s_se[w] = se; }
    __syncthreads();

    if (t == 0) {
        float sqt = s_sq[0] + s_sq[1] + s_sq[2] + s_sq[3];
        float set = s_se[0] + s_se[1] + s_se[2] + s_se[3];
        int lb = lab64 ? (int)((const long long*)labraw)[row]
                       : ((const int*)labraw)[row];
        g_sq[row]  = sqt;
        g_ce[row]  = mx + logf(set) - xr[lb];
        g_lab[row] = lb;
        g_sc[row]  = ma / 127.0f;
        g_pos[row] = f2ord(-dev_inf());
        g_neg[row] = f2ord(dev_inf());
    }

#pragma unroll
    for (int i = 0; i < 4; i++) {
        int q = __float2int_rn(v[i] * qinv);
        g_q[(size_t)row * DIM + t + 128 * i] = (signed char)q;
    }
}

// ---------------- mma helpers ----------------------------------------------
__device__ __forceinline__ void ldm_x4(uint32_t* d, uint32_t addr) {
    asm volatile("ldmatrix.sync.aligned.m8n8.x4.shared.b16 {%0,%1,%2,%3}, [%4];\n"
                 : "=r"(d[0]), "=r"(d[1]), "=r"(d[2]), "=r"(d[3]) : "r"(addr));
}
__device__ __forceinline__ void mma16832(int* c, const uint32_t* a, const uint32_t* b) {
    asm volatile(
        "mma.sync.aligned.m16n8k32.row.col.s32.s8.s8.s32 "
        "{%0,%1,%2,%3}, {%4,%5,%6,%7}, {%8,%9}, {%0,%1,%2,%3};\n"
        : "+r"(c[0]), "+r"(c[1]), "+r"(c[2]), "+r"(c[3])
        : "r"(a[0]), "r"(a[1]), "r"(a[2]), "r"(a[3]), "r"(b[0]), "r"(b[1]));
}
__device__ __forceinline__ void cpasync16(uint32_t dst, const void* src) {
    asm volatile("cp.async.cg.shared.global [%0], [%1], 16;" :: "r"(dst), "l"(src));
}

// swizzled 16B-chunk byte offset for (row r, logical chunk c), 128B rows
__device__ __forceinline__ uint32_t swz8(int r, int c) {
    return (uint32_t)((r * 8 + (c ^ (r & 7))) << 4);
}

// ---------------- fused triangular GEMM + masked max/min + finalize --------
__global__ void __launch_bounds__(256, 2) gemm_kernel(float* out) {
    extern __shared__ __align__(1024) char smdyn[];
    __shared__ __align__(8) unsigned long long s_mbar[2 * NSTAGE]; // full[3], empty[3]
    __shared__ float s_sqi[128], s_sqj[128], s_sci[128], s_scj[128];
    __shared__ int   s_li[128], s_lj[128];

    // map linear block -> upper-triangular tile (bi <= bj)
    int b = blockIdx.x;
    int bi = 0;
    while ((bi + 1) * BT - ((bi + 1) * bi) / 2 <= b) bi++;
    int bj = bi + (b - (bi * BT - (bi * (bi - 1)) / 2));

    const int tid  = threadIdx.x;
    const int lane = tid & 31, warp = tid >> 5;
    const int wm = warp & 3, wn = warp >> 2;   // 4x2 warp grid: 32-row x 64-col per warp

    const int rowi0 = bi * 128, rowj0 = bj * 128;

    uint32_t smem0, mbar0;
    asm("{ .reg .u64 t; cvta.to.shared.u64 t, %1; cvt.u32.u64 %0, t; }"
        : "=r"(smem0) : "l"(smdyn));
    asm("{ .reg .u64 t; cvta.to.shared.u64 t, %1; cvt.u32.u64 %0, t; }"
        : "=r"(mbar0) : "l"(s_mbar));
    // full[s] = mbar0 + s*8 ; empty[s] = mbar0 + 24 + s*8

    if (tid == 0) {
#pragma unroll
        for (int s = 0; s < NSTAGE; s++) {
            MBAR_INIT(mbar0 + s * 8, 256);        // full: 256 cp-async arrives
            MBAR_INIT(mbar0 + 24 + s * 8, 256);   // empty: 256 thread arrives
        }
    }
    __syncthreads();

    auto issue_chunk = [&](int k, int stage) {
        const int kt = k * KC;
        const uint32_t sbA = smem0 + stage * STAGEB;
        const uint32_t sbB = sbA + TILEB;
#pragma unroll
        for (int rep = 0; rep < 4; rep++) {
            int q = rep * 256 + tid;            // 0..1023 (128 rows x 8 chunks)
            int r = q >> 3, c = q & 7;
            uint32_t so = swz8(r, c);
            size_t ga = (size_t)(rowi0 + r) * DIM + kt + c * 16;
            size_t gb = (size_t)(rowj0 + r) * DIM + kt + c * 16;
            cpasync16(sbA + so, g_q + ga);
            cpasync16(sbB + so, g_q + gb);
        }
        CP_MBAR_ARRIVE(mbar0 + stage * 8);
    };

    issue_chunk(0, 0);
    issue_chunk(1, 1);
    issue_chunk(2, 2);

    if (tid < 128) {
        s_sqi[tid] = g_sq[rowi0 + tid];
        s_sci[tid] = g_sc[rowi0 + tid];
        s_li[tid]  = g_lab[rowi0 + tid];
    } else {
        int t2 = tid - 128;
        s_sqj[t2] = g_sq[rowj0 + t2];
        s_scj[t2] = g_sc[rowj0 + t2];
        s_lj[t2]  = g_lab[rowj0 + t2];
    }

    int acc[2][8][4];
#pragma unroll
    for (int mi = 0; mi < 2; mi++)
#pragma unroll
        for (int ni = 0; ni < 8; ni++)
#pragma unroll
            for (int k = 0; k < 4; k++) acc[mi][ni][k] = 0;

    const int m4 = lane >> 3, ri = lane & 7;

    for (int k = 0; k < NCH; k++) {
        const int st = k % NSTAGE;
        const int ph = (k / NSTAGE) & 1;
        MBAR_WAIT(mbar0 + st * 8, ph);           // wait full

        const uint32_t baseA = smem0 + st * STAGEB;
        const uint32_t baseB = baseA + TILEB;

#pragma unroll
        for (int ks = 0; ks < 4; ks++) {         // 4 k-steps of k32 int8
            uint32_t ah[2][4];
#pragma unroll
            for (int mi = 0; mi < 2; mi++) {
                int r = wm * 32 + mi * 16 + (m4 & 1) * 8 + ri;
                int c = ks * 2 + (m4 >> 1);
                ldm_x4(ah[mi], baseA + swz8(r, c));
            }
            uint32_t bh[4][4];
#pragma unroll
            for (int p4 = 0; p4 < 4; p4++) {
                int r = wn * 64 + p4 * 16 + (m4 >> 1) * 8 + ri;
                int c = ks * 2 + (m4 & 1);
                ldm_x4(bh[p4], baseB + swz8(r, c));
            }
#pragma unroll
            for (int mi = 0; mi < 2; mi++)
#pragma unroll
                for (int ni = 0; ni < 8; ni++)
                    mma16832(acc[mi][ni], ah[mi], &bh[ni >> 1][(ni & 1) * 2]);
        }

        MBAR_ARRIVE(mbar0 + 24 + st * 8);        // arrive empty (reads done)

        if (k + NSTAGE < NCH) {
            MBAR_WAIT(mbar0 + 24 + st * 8, ph);  // all threads done reading stage
            issue_chunk(k + NSTAGE, st);
        }
    }

    // ---------------- epilogue: dist + masked max/min reductions -----------
    const int g = lane >> 2, tg = lane & 3;
    const float NEG = -dev_inf(), POS = dev_inf();
    float rmax[2][2], rmin[2][2];
#pragma unroll
    for (int mi = 0; mi < 2; mi++)
#pragma unroll
        for (int h = 0; h < 2; h++) { rmax[mi][h] = NEG; rmin[mi][h] = POS; }
    float cmx[16], cmn[16];
#pragma unroll
    for (int s = 0; s < 16; s++) { cmx[s] = NEG; cmn[s] = POS; }

#pragma unroll
    for (int mi = 0; mi < 2; mi++)
#pragma unroll
        for (int h = 0; h < 2; h++) {
            int li = wm * 32 + mi * 16 + h * 8 + g;
            int labi = s_li[li];
            float sqi = s_sqi[li];
            float sci2 = 2.0f * s_sci[li];
#pragma unroll
            for (int ni = 0; ni < 8; ni++)
#pragma unroll
                for (int cc = 0; cc < 2; cc++) {
                    int lj = wn * 64 + ni * 8 + tg * 2 + cc;
                    float d = sqi + s_sqj[lj]
                            - sci2 * s_scj[lj] * (float)acc[mi][ni][h * 2 + cc];
                    int s = ni * 2 + cc;
                    if (labi == s_lj[lj]) {
                        rmax[mi][h] = fmaxf(rmax[mi][h], d);
                        cmx[s] = fmaxf(cmx[s], d);
                    } else {
                        rmin[mi][h] = fminf(rmin[mi][h], d);
                        cmn[s] = fminf(cmn[s], d);
                    }
                }
        }

    // row reduction: lanes sharing g differ in tg (low 2 bits)
#pragma unroll
    for (int mi = 0; mi < 2; mi++)
#pragma unroll
        for (int h = 0; h < 2; h++) {
            float m_ = rmax[mi][h], n_ = rmin[mi][h];
            m_ = fmaxf(m_, __shfl_xor_sync(0xffffffffu, m_, 1));
            m_ = fmaxf(m_, __shfl_xor_sync(0xffffffffu, m_, 2));
            n_ = fminf(n_, __shfl_xor_sync(0xffffffffu, n_, 1));
            n_ = fminf(n_, __shfl_xor_sync(0xffffffffu, n_, 2));
            if (tg == 0) {
                int grow = rowi0 + wm * 32 + mi * 16 + h * 8 + g;
                atomicMax(&g_pos[grow], f2ord(m_));
                atomicMin(&g_neg[grow], f2ord(n_));
            }
        }

    // column reduction (symmetry): lanes sharing tg differ in g (bits 2..4)
    if (bi != bj) {
#pragma unroll
        for (int s = 0; s < 16; s++) {
            float m_ = cmx[s], n_ = cmn[s];
            m_ = fmaxf(m_, __shfl_xor_sync(0xffffffffu, m_, 4));
            m_ = fmaxf(m_, __shfl_xor_sync(0xffffffffu, m_, 8));
            m_ = fmaxf(m_, __shfl_xor_sync(0xffffffffu, m_, 16));
            n_ = fminf(n_, __shfl_xor_sync(0xffffffffu, n_, 4));
            n_ = fminf(n_, __shfl_xor_sync(0xffffffffu, n_, 8));
            n_ = fminf(n_, __shfl_xor_sync(0xffffffffu, n_, 16));
            if (g == 0) {
                int gcol = rowj0 + wn * 64 + (s >> 1) * 8 + tg * 2 + (s & 1);
                atomicMax(&g_pos[gcol], f2ord(m_));
                atomicMin(&g_neg[gcol], f2ord(n_));
            }
        }
    }

    // ---------------- last-block finalize (deterministic tree) -------------
    __shared__ unsigned s_last;
    __syncthreads();
    if (tid == 0) {
        __threadfence();
        s_last = (atomicAdd(&g_done, 1u) == (unsigned)(NTILES - 1));
    }
    __syncthreads();
    if (s_last) {
        __shared__ float sh[256];
        float ts = 0.f, cs = 0.f;
        for (int i = tid; i < N_ROWS; i += 256) {
            float p = ord2f(__ldcg(&g_pos[i]));
            float n = ord2f(__ldcg(&g_neg[i]));
            ts += fmaxf(p - n + MARGIN, 0.0f);
            cs += __ldcg(&g_ce[i]);
        }
        sh[tid] = ts; __syncthreads();
        for (int o = 128; o; o >>= 1) { if (tid < o) sh[tid] += sh[tid + o]; __syncthreads(); }
        float tt = sh[0]; __syncthreads();
        sh[tid] = cs; __syncthreads();
        for (int o = 128; o; o >>= 1) { if (tid < o) sh[tid] += sh[tid + o]; __syncthreads(); }
        if (tid == 0) {
            out[0] = tt / (float)N_ROWS + sh[0] / (float)N_ROWS;
            g_done = 0;
            __threadfence();
        }
    }
}

// ---------------- entry -----------------------------------------------------
extern "C" void kernel_launch(void* const* d_in, const int* in_sizes, int n_in,
                              void* d_out, int out_size) {
    const float* x   = (const float*)d_in[0];
    const void*  lab = d_in[1];

    cudaFuncSetAttribute(gemm_kernel, cudaFuncAttributeMaxDynamicSharedMemorySize, SMEMDYN);
    prep_kernel<<<N_ROWS, 128>>>(x, lab);
    gemm_kernel<<<NTILES, 256, SMEMDYN>>>((float*)d_out);
}

// round 9
// speedup vs baseline: 1.6836x; 1.6836x over previous
#include <cuda_runtime.h>
#include <cuda_fp16.h>
#include <cstdint>

#define N_ROWS 8192
#define DIM    512
#define BT     64            // 8192/128 tiles per dimension
#define MARGIN 0.35f
#define KC     64            // K elems per smem chunk (128B rows)
#define NCH    (DIM / KC)    // 8
#define TILEB  (128 * KC * 2)       // 16384 per operand tile
#define STAGEB (2 * TILEB)          // A + B = 32768
#define NSTAGE 3
#define SMEMDYN (NSTAGE * STAGEB)   // 98304
#define NTILES ((BT * (BT + 1)) / 2)
#define NTHR   288                  // 8 consumer warps + 1 producer warp

// ---------------- scratch (device globals; no allocation allowed) ----------
__device__ __align__(16) __half g_h[N_ROWS * DIM];
__device__ float    g_sq[N_ROWS];
__device__ float    g_ce[N_ROWS];
__device__ unsigned g_pos[N_ROWS];
__device__ unsigned g_neg[N_ROWS];
__device__ int      g_lab[N_ROWS];
__device__ unsigned g_done;          // zero-init; finalizer re-zeros for graph replay

// ---------------- float <-> monotone unsigned encoding ---------------------
__device__ __forceinline__ unsigned f2ord(float f) {
    unsigned u = __float_as_uint(f);
    return (u & 0x80000000u) ? ~u : (u | 0x80000000u);
}
__device__ __forceinline__ float ord2f(unsigned u) {
    unsigned b = (u & 0x80000000u) ? (u ^ 0x80000000u) : ~u;
    return __uint_as_float(b);
}
__device__ __forceinline__ float dev_inf() { return __int_as_float(0x7f800000); }

// ---------------- mbarrier helpers ------------------------------------------
#define MBAR_INIT(a, c) \
    asm volatile("mbarrier.init.shared.b64 [%0], %1;" :: "r"((uint32_t)(a)), "r"((uint32_t)(c)) : "memory")
#define MBAR_ARRIVE(a) \
    asm volatile("mbarrier.arrive.shared.b64 _, [%0];" :: "r"((uint32_t)(a)) : "memory")
#define CP_MBAR_ARRIVE(a) \
    asm volatile("cp.async.mbarrier.arrive.noinc.shared.b64 [%0];" :: "r"((uint32_t)(a)) : "memory")
#define MBAR_WAIT(a, ph) do {                                                          \
    uint32_t _m = (uint32_t)(a), _p = (uint32_t)(ph), _d;                              \
    asm volatile("{ .reg .pred p; mbarrier.try_wait.parity.acquire.cta.shared::cta.b64 p, [%1], %2;" \
                 " selp.b32 %0, 1, 0, p; }" : "=r"(_d) : "r"(_m), "r"(_p) : "memory"); \
    if (!_d) {                                                                         \
        asm volatile("{ .reg .pred P1; WL_%=: mbarrier.try_wait.parity.acquire.cta.shared::cta.b64 P1, [%0], %1, 0x989680;" \
                     " @P1 bra.uni WD_%=; bra.uni WL_%=; WD_%=: }" :: "r"(_m), "r"(_p) : "memory"); \
    } } while (0)

// ---------------- prep: norms, CE, fp16 cast, label detect, init -----------
__global__ void prep_kernel(const float* __restrict__ x, const void* __restrict__ labraw) {
    int row = blockIdx.x;
    int t   = threadIdx.x;          // 128 threads
    const float* xr = x + (size_t)row * DIM;

    // int64 labels in [0,512) -> every odd 32-bit word is zero (per-block vote).
    const int* raw32 = (const int*)labraw;
    int lab64 = !__syncthreads_or(raw32[2 * t + 1] != 0);

    float v[4];
#pragma unroll
    for (int i = 0; i < 4; i++) v[i] = xr[t + 128 * i];

    float ss = 0.f, mx = -dev_inf();
#pragma unroll
    for (int i = 0; i < 4; i++) { ss += v[i] * v[i]; mx = fmaxf(mx, v[i]); }
#pragma unroll
    for (int o = 16; o; o >>= 1) {
        ss += __shfl_xor_sync(0xffffffffu, ss, o);
        mx  = fmaxf(mx, __shfl_xor_sync(0xffffffffu, mx, o));
    }
    __shared__ float s_ss[4], s_mx[4], s_sq[4], s_se[4];
    int w = t >> 5, l = t & 31;
    if (l == 0) { s_ss[w] = ss; s_mx[w] = mx; }
    __syncthreads();
    ss = s_ss[0] + s_ss[1] + s_ss[2] + s_ss[3];
    mx = fmaxf(fmaxf(s_mx[0], s_mx[1]), fmaxf(s_mx[2], s_mx[3]));

    float norm = sqrtf(ss);
    float sq = 0.f, se = 0.f;
#pragma unroll
    for (int i = 0; i < 4; i++) {
        float xn = v[i] / norm;
        sq += xn * xn;
        se += expf(v[i] - mx);
    }
#pragma unroll
    for (int o = 16; o; o >>= 1) {
        sq += __shfl_xor_sync(0xffffffffu, sq, o);
        se += __shfl_xor_sync(0xffffffffu, se, o);
    }
    if (l == 0) { s_sq[w] = sq; s_se[w] = se; }
    __syncthreads();

    if (t == 0) {
        float sqt = s_sq[0] + s_sq[1] + s_sq[2] + s_sq[3];
        float set = s_se[0] + s_se[1] + s_se[2] + s_se[3];
        int lb = lab64 ? (int)((const long long*)labraw)[row]
                       : ((const int*)labraw)[row];
        g_sq[row]  = sqt;
        g_ce[row]  = mx + logf(set) - xr[lb];
        g_lab[row] = lb;
        g_pos[row] = f2ord(-dev_inf());
        g_neg[row] = f2ord(dev_inf());
    }

#pragma unroll
    for (int i = 0; i < 4; i++)
        g_h[(size_t)row * DIM + t + 128 * i] = __float2half_rn(v[i]);
}

// ---------------- mma helpers ----------------------------------------------
__device__ __forceinline__ void ldm_x4(uint32_t* d, uint32_t addr) {
    asm volatile("ldmatrix.sync.aligned.m8n8.x4.shared.b16 {%0,%1,%2,%3}, [%4];\n"
                 : "=r"(d[0]), "=r"(d[1]), "=r"(d[2]), "=r"(d[3]) : "r"(addr));
}
__device__ __forceinline__ void mma16816(float* c, const uint32_t* a, const uint32_t* b) {
    asm volatile(
        "mma.sync.aligned.m16n8k16.row.col.f32.f16.f16.f32 "
        "{%0,%1,%2,%3}, {%4,%5,%6,%7}, {%8,%9}, {%0,%1,%2,%3};\n"
        : "+f"(c[0]), "+f"(c[1]), "+f"(c[2]), "+f"(c[3])
        : "r"(a[0]), "r"(a[1]), "r"(a[2]), "r"(a[3]), "r"(b[0]), "r"(b[1]));
}
__device__ __forceinline__ void cpasync16(uint32_t dst, const void* src) {
    asm volatile("cp.async.cg.shared.global [%0], [%1], 16;" :: "r"(dst), "l"(src));
}

// swizzled 16B-chunk byte offset for (row r, logical chunk c) in 128x64 fp16 tile
__device__ __forceinline__ uint32_t swz8(int r, int c) {
    return (uint32_t)((r * 8 + (c ^ (r & 7))) << 4);
}

// ---------------- fused triangular GEMM + masked max/min + finalize --------
__global__ void __launch_bounds__(NTHR, 2) gemm_kernel(float* out) {
    extern __shared__ __align__(1024) char smdyn[];
    __shared__ __align__(8) unsigned long long s_mbar[2 * NSTAGE]; // full[3], empty[3]
    __shared__ float s_sqi[128], s_sqj[128];
    __shared__ int   s_li[128], s_lj[128];
    __shared__ float shw[18];

    // map linear block -> upper-triangular tile (bi <= bj)
    int b = blockIdx.x;
    int bi = 0;
    while ((bi + 1) * BT - ((bi + 1) * bi) / 2 <= b) bi++;
    int bj = bi + (b - (bi * BT - (bi * (bi - 1)) / 2));

    const int tid  = threadIdx.x;
    const int lane = tid & 31, warp = tid >> 5;

    const int rowi0 = bi * 128, rowj0 = bj * 128;

    uint32_t smem0, mbar0;
    asm("{ .reg .u64 t; cvta.to.shared.u64 t, %1; cvt.u32.u64 %0, t; }"
        : "=r"(smem0) : "l"(smdyn));
    asm("{ .reg .u64 t; cvta.to.shared.u64 t, %1; cvt.u32.u64 %0, t; }"
        : "=r"(mbar0) : "l"(s_mbar));
    // full[s] = mbar0 + s*8 ; empty[s] = mbar0 + 24 + s*8

    if (tid == 0) {
#pragma unroll
        for (int s = 0; s < NSTAGE; s++) {
            MBAR_INIT(mbar0 + s * 8, 32);         // full: 32 producer cp-async arrives
            MBAR_INIT(mbar0 + 24 + s * 8, 256);   // empty: 256 consumer arrives
        }
    }
    if (tid < 128) { s_sqi[tid] = g_sq[rowi0 + tid]; s_li[tid] = g_lab[rowi0 + tid]; }
    else if (tid < 256) {
        int t2 = tid - 128;
        s_sqj[t2] = g_sq[rowj0 + t2]; s_lj[t2] = g_lab[rowj0 + t2];
    }
    __syncthreads();

    if (warp == 8) {
        // ================= producer warp: owns all loads + empty waits ======
        for (int k = 0; k < NCH; k++) {
            const int st = k % NSTAGE;
            if (k >= NSTAGE) MBAR_WAIT(mbar0 + 24 + st * 8, ((k / NSTAGE) + 1) & 1);
            const int kt = k * KC;
            const uint32_t sbA = smem0 + st * STAGEB;
            const uint32_t sbB = sbA + TILEB;
#pragma unroll 4
            for (int rep = 0; rep < 32; rep++) {
                int q = rep * 32 + lane;          // 0..1023
                int r = q >> 3, c = q & 7;
                uint32_t so = swz8(r, c);
                cpasync16(sbA + so, g_h + (size_t)(rowi0 + r) * DIM + kt + c * 8);
                cpasync16(sbB + so, g_h + (size_t)(rowj0 + r) * DIM + kt + c * 8);
            }
            CP_MBAR_ARRIVE(mbar0 + st * 8);
        }
    } else {
        // ================= consumer warps: pure LDSM + MMA ==================
        const int wm = warp & 3, wn = warp >> 2;  // 4x2 grid: 32-row x 64-col warp tile
        const int m4 = lane >> 3, ri = lane & 7;

        float acc[2][8][4];
#pragma unroll
        for (int mi = 0; mi < 2; mi++)
#pragma unroll
            for (int ni = 0; ni < 8; ni++)
#pragma unroll
                for (int k = 0; k < 4; k++) acc[mi][ni][k] = 0.f;

        for (int k = 0; k < NCH; k++) {
            const int st = k % NSTAGE;
            MBAR_WAIT(mbar0 + st * 8, (k / NSTAGE) & 1);   // data ready

            const uint32_t baseA = smem0 + st * STAGEB;
            const uint32_t baseB = baseA + TILEB;

#pragma unroll
            for (int kk = 0; kk < 4; kk++) {
                uint32_t ah[2][4];
#pragma unroll
                for (int mi = 0; mi < 2; mi++) {
                    int r = wm * 32 + mi * 16 + (m4 & 1) * 8 + ri;
                    int c = kk * 2 + (m4 >> 1);
                    ldm_x4(ah[mi], baseA + swz8(r, c));
                }
                uint32_t bh[4][4];
#pragma unroll
                for (int p4 = 0; p4 < 4; p4++) {
                    int r = wn * 64 + p4 * 16 + (m4 >> 1) * 8 + ri;
                    int c = kk * 2 + (m4 & 1);
                    ldm_x4(bh[p4], baseB + swz8(r, c));
                }
#pragma unroll
                for (int mi = 0; mi < 2; mi++)
#pragma unroll
                    for (int ni = 0; ni < 8; ni++)
                        mma16816(acc[mi][ni], ah[mi], &bh[ni >> 1][(ni & 1) * 2]);
            }

            MBAR_ARRIVE(mbar0 + 24 + st * 8);    // this warp done with stage
        }

        // ------------- epilogue: dist + masked max/min reductions ----------
        const int g = lane >> 2, tg = lane & 3;
        const float NEG = -dev_inf(), POS = dev_inf();
        float cmx[16], cmn[16];
#pragma unroll
        for (int s = 0; s < 16; s++) { cmx[s] = NEG; cmn[s] = POS; }

#pragma unroll
        for (int mi = 0; mi < 2; mi++)
#pragma unroll
            for (int h = 0; h < 2; h++) {
                int li = wm * 32 + mi * 16 + h * 8 + g;
                int labi = s_li[li];
                float sqi = s_sqi[li];
                float rmax = NEG, rmin = POS;
#pragma unroll
                for (int ni = 0; ni < 8; ni++)
#pragma unroll
                    for (int cc = 0; cc < 2; cc++) {
                        int lj = wn * 64 + ni * 8 + tg * 2 + cc;
                        float d = sqi + s_sqj[lj] - 2.0f * acc[mi][ni][h * 2 + cc];
                        int s = ni * 2 + cc;
                        if (labi == s_lj[lj]) {
                            rmax = fmaxf(rmax, d);
                            cmx[s] = fmaxf(cmx[s], d);
                        } else {
                            rmin = fminf(rmin, d);
                            cmn[s] = fminf(cmn[s], d);
                        }
                    }
                // row reduction across tg (low 2 lane bits)
                rmax = fmaxf(rmax, __shfl_xor_sync(0xffffffffu, rmax, 1));
                rmax = fmaxf(rmax, __shfl_xor_sync(0xffffffffu, rmax, 2));
                rmin = fminf(rmin, __shfl_xor_sync(0xffffffffu, rmin, 1));
                rmin = fminf(rmin, __shfl_xor_sync(0xffffffffu, rmin, 2));
                if (tg == 0) {
                    int grow = rowi0 + li;
                    atomicMax(&g_pos[grow], f2ord(rmax));
                    atomicMin(&g_neg[grow], f2ord(rmin));
                }
            }

        // column reduction (symmetry): lanes sharing tg differ in g (bits 2..4)
        if (bi != bj) {
#pragma unroll
            for (int s = 0; s < 16; s++) {
                float m_ = cmx[s], n_ = cmn[s];
                m_ = fmaxf(m_, __shfl_xor_sync(0xffffffffu, m_, 4));
                m_ = fmaxf(m_, __shfl_xor_sync(0xffffffffu, m_, 8));
                m_ = fmaxf(m_, __shfl_xor_sync(0xffffffffu, m_, 16));
                n_ = fminf(n_, __shfl_xor_sync(0xffffffffu, n_, 4));
                n_ = fminf(n_, __shfl_xor_sync(0xffffffffu, n_, 8));
                n_ = fminf(n_, __shfl_xor_sync(0xffffffffu, n_, 16));
                if (g == 0) {
                    int gcol = rowj0 + wn * 64 + (s >> 1) * 8 + tg * 2 + (s & 1);
                    atomicMax(&g_pos[gcol], f2ord(m_));
                    atomicMin(&g_neg[gcol], f2ord(n_));
                }
            }
        }
    }

    // ---------------- last-block finalize (deterministic) -------------------
    __shared__ unsigned s_last;
    __threadfence();                       // make this thread's atomics visible
    __syncthreads();
    if (tid == 0)
        s_last = (atomicAdd(&g_done, 1u) == (unsigned)(NTILES - 1));
    __syncthreads();
    if (s_last) {
        float ts = 0.f, cs = 0.f;
        for (int i = tid; i < N_ROWS; i += NTHR) {
            float p = ord2f(__ldcg(&g_pos[i]));
            float n = ord2f(__ldcg(&g_neg[i]));
            ts += fmaxf(p - n + MARGIN, 0.0f);
            cs += __ldcg(&g_ce[i]);
        }
#pragma unroll
        for (int o = 16; o; o >>= 1) {
            ts += __shfl_xor_sync(0xffffffffu, ts, o);
            cs += __shfl_xor_sync(0xffffffffu, cs, o);
        }
        if (lane == 0) { shw[warp] = ts; shw[9 + warp] = cs; }
        __syncthreads();
        if (tid == 0) {
            float tt = 0.f, ct = 0.f;
#pragma unroll
            for (int w = 0; w < 9; w++) { tt += shw[w]; ct += shw[9 + w]; }
            out[0] = tt / (float)N_ROWS + ct / (float)N_ROWS;
            g_done = 0;
            __threadfence();
        }
    }
}

// ---------------- entry -----------------------------------------------------
extern "C" void kernel_launch(void* const* d_in, const int* in_sizes, int n_in,
                              void* d_out, int out_size) {
    const float* x   = (const float*)d_in[0];
    const void*  lab = d_in[1];

    cudaFuncSetAttribute(gemm_kernel, cudaFuncAttributeMaxDynamicSharedMemorySize, SMEMDYN);
    prep_kernel<<<N_ROWS, 128>>>(x, lab);
    gemm_kernel<<<NTILES, NTHR, SMEMDYN>>>((float*)d_out);
}

// round 10
// speedup vs baseline: 2.0248x; 1.2027x over previous
#include <cuda_runtime.h>
#include <cuda_fp16.h>
#include <cstdint>

#define N_ROWS 8192
#define DIM    512
#define BT     64            // 8192/128 tiles per dimension
#define MARGIN 0.35f
#define KC     32            // K elems per smem chunk (64B rows)
#define NCH    (DIM / KC)    // 16
#define TILEB  (128 * KC * 2)       // 8192 per operand tile
#define STAGEB (2 * TILEB)          // A + B = 16384
#define NSTAGE 6
#define SMEMDYN (NSTAGE * STAGEB)   // 98304
#define NTILES ((BT * (BT + 1)) / 2)

// ---------------- scratch (device globals; no allocation allowed) ----------
__device__ __align__(16) __half g_h[N_ROWS * DIM];
__device__ float    g_sq[N_ROWS];
__device__ float    g_ce[N_ROWS];
__device__ unsigned g_pos[N_ROWS];
__device__ unsigned g_neg[N_ROWS];
__device__ int      g_lab[N_ROWS];
__device__ unsigned g_done;          // zero-init; finalizer re-zeros for graph replay

// ---------------- float <-> monotone unsigned encoding ---------------------
__device__ __forceinline__ unsigned f2ord(float f) {
    unsigned u = __float_as_uint(f);
    return (u & 0x80000000u) ? ~u : (u | 0x80000000u);
}
__device__ __forceinline__ float ord2f(unsigned u) {
    unsigned b = (u & 0x80000000u) ? (u ^ 0x80000000u) : ~u;
    return __uint_as_float(b);
}
__device__ __forceinline__ float dev_inf() { return __int_as_float(0x7f800000); }

// ---------------- mbarrier helpers ------------------------------------------
#define MBAR_INIT(a, c) \
    asm volatile("mbarrier.init.shared.b64 [%0], %1;" :: "r"((uint32_t)(a)), "r"((uint32_t)(c)) : "memory")
#define MBAR_ARRIVE(a) \
    asm volatile("mbarrier.arrive.shared.b64 _, [%0];" :: "r"((uint32_t)(a)) : "memory")
#define CP_MBAR_ARRIVE(a) \
    asm volatile("cp.async.mbarrier.arrive.noinc.shared.b64 [%0];" :: "r"((uint32_t)(a)) : "memory")
#define MBAR_WAIT(a, ph) do {                                                          \
    uint32_t _m = (uint32_t)(a), _p = (uint32_t)(ph), _d;                              \
    asm volatile("{ .reg .pred p; mbarrier.try_wait.parity.acquire.cta.shared::cta.b64 p, [%1], %2;" \
                 " selp.b32 %0, 1, 0, p; }" : "=r"(_d) : "r"(_m), "r"(_p) : "memory"); \
    if (!_d) {                                                                         \
        asm volatile("{ .reg .pred P1; WL_%=: mbarrier.try_wait.parity.acquire.cta.shared::cta.b64 P1, [%0], %1, 0x989680;" \
                     " @P1 bra.uni WD_%=; bra.uni WL_%=; WD_%=: }" :: "r"(_m), "r"(_p) : "memory"); \
    } } while (0)

// ---------------- prep: norms, CE, fp16 cast, label detect, init -----------
__global__ void prep_kernel(const float* __restrict__ x, const void* __restrict__ labraw) {
    int row = blockIdx.x;
    int t   = threadIdx.x;          // 128 threads
    const float* xr = x + (size_t)row * DIM;

    // int64 labels in [0,512) -> every odd 32-bit word is zero (per-block vote).
    const int* raw32 = (const int*)labraw;
    int lab64 = !__syncthreads_or(raw32[2 * t + 1] != 0);

    float v[4];
#pragma unroll
    for (int i = 0; i < 4; i++) v[i] = xr[t + 128 * i];

    float ss = 0.f, mx = -dev_inf();
#pragma unroll
    for (int i = 0; i < 4; i++) { ss += v[i] * v[i]; mx = fmaxf(mx, v[i]); }
#pragma unroll
    for (int o = 16; o; o >>= 1) {
        ss += __shfl_xor_sync(0xffffffffu, ss, o);
        mx  = fmaxf(mx, __shfl_xor_sync(0xffffffffu, mx, o));
    }
    __shared__ float s_ss[4], s_mx[4], s_sq[4], s_se[4];
    int w = t >> 5, l = t & 31;
    if (l == 0) { s_ss[w] = ss; s_mx[w] = mx; }
    __syncthreads();
    ss = s_ss[0] + s_ss[1] + s_ss[2] + s_ss[3];
    mx = fmaxf(fmaxf(s_mx[0], s_mx[1]), fmaxf(s_mx[2], s_mx[3]));

    float norm = sqrtf(ss);
    float sq = 0.f, se = 0.f;
#pragma unroll
    for (int i = 0; i < 4; i++) {
        float xn = v[i] / norm;
        sq += xn * xn;
        se += expf(v[i] - mx);
    }
#pragma unroll
    for (int o = 16; o; o >>= 1) {
        sq += __shfl_xor_sync(0xffffffffu, sq, o);
        se += __shfl_xor_sync(0xffffffffu, se, o);
    }
    if (l == 0) { s_sq[w] = sq; s_se[w] = se; }
    __syncthreads();

    if (t == 0) {
        float sqt = s_sq[0] + s_sq[1] + s_sq[2] + s_sq[3];
        float set = s_se[0] + s_se[1] + s_se[2] + s_se[3];
        int lb = lab64 ? (int)((const long long*)labraw)[row]
                       : ((const int*)labraw)[row];
        g_sq[row]  = sqt;
        g_ce[row]  = mx + logf(set) - xr[lb];
        g_lab[row] = lb;
        g_pos[row] = f2ord(-dev_inf());
        g_neg[row] = f2ord(dev_inf());
    }

#pragma unroll
    for (int i = 0; i < 4; i++)
        g_h[(size_t)row * DIM + t + 128 * i] = __float2half_rn(v[i]);
}

// ---------------- mma helpers ----------------------------------------------
__device__ __forceinline__ void ldm_x4(uint32_t* d, uint32_t addr) {
    asm volatile("ldmatrix.sync.aligned.m8n8.x4.shared.b16 {%0,%1,%2,%3}, [%4];\n"
                 : "=r"(d[0]), "=r"(d[1]), "=r"(d[2]), "=r"(d[3]) : "r"(addr));
}
__device__ __forceinline__ void mma16816(float* c, const uint32_t* a, const uint32_t* b) {
    asm volatile(
        "mma.sync.aligned.m16n8k16.row.col.f32.f16.f16.f32 "
        "{%0,%1,%2,%3}, {%4,%5,%6,%7}, {%8,%9}, {%0,%1,%2,%3};\n"
        : "+f"(c[0]), "+f"(c[1]), "+f"(c[2]), "+f"(c[3])
        : "r"(a[0]), "r"(a[1]), "r"(a[2]), "r"(a[3]), "r"(b[0]), "r"(b[1]));
}
__device__ __forceinline__ void cpasync16(uint32_t dst, const void* src) {
    asm volatile("cp.async.cg.shared.global [%0], [%1], 16;" :: "r"(dst), "l"(src));
}

// swizzled 16B-chunk index for (row r, logical chunk c) inside a 128x32 fp16 tile
__device__ __forceinline__ uint32_t swz4(int r, int c) {
    return (uint32_t)((r * 4 + (c ^ ((r >> 1) & 3))) << 4);
}

// ---------------- fused triangular GEMM + masked max/min + finalize --------
__global__ void __launch_bounds__(256, 2) gemm_kernel(float* out) {
    extern __shared__ __align__(1024) char smdyn[];
    __shared__ __align__(8) unsigned long long s_mbar[2 * NSTAGE]; // full[6], empty[6]
    __shared__ float s_sqi[128], s_sqj[128];
    __shared__ int   s_li[128], s_lj[128];
    __shared__ float shw[16];

    // map linear block -> upper-triangular tile (bi <= bj)
    int b = blockIdx.x;
    int bi = 0;
    while ((bi + 1) * BT - ((bi + 1) * bi) / 2 <= b) bi++;
    int bj = bi + (b - (bi * BT - (bi * (bi - 1)) / 2));

    const int tid  = threadIdx.x;
    const int lane = tid & 31, warp = tid >> 5;
    const int wm = warp & 3, wn = warp >> 2;   // 4x2 warp grid: 32-row x 64-col per warp

    const int rowi0 = bi * 128, rowj0 = bj * 128;

    uint32_t smem0, mbar0;
    asm("{ .reg .u64 t; cvta.to.shared.u64 t, %1; cvt.u32.u64 %0, t; }"
        : "=r"(smem0) : "l"(smdyn));
    asm("{ .reg .u64 t; cvta.to.shared.u64 t, %1; cvt.u32.u64 %0, t; }"
        : "=r"(mbar0) : "l"(s_mbar));
    // full[s] = mbar0 + s*8 ; empty[s] = mbar0 + 48 + s*8

    if (tid == 0) {
#pragma unroll
        for (int s = 0; s < NSTAGE; s++) {
            MBAR_INIT(mbar0 + s * 8, 256);        // full: 256 cp-async arrives
            MBAR_INIT(mbar0 + 48 + s * 8, 256);   // empty: 256 consumer arrives
        }
    }
    if (tid < 128) { s_sqi[tid] = g_sq[rowi0 + tid]; s_li[tid] = g_lab[rowi0 + tid]; }
    else { int t2 = tid - 128; s_sqj[t2] = g_sq[rowj0 + t2]; s_lj[t2] = g_lab[rowj0 + t2]; }
    __syncthreads();

    // per-thread load geometry: 2 x 16B per operand per chunk
    const int r0 = tid >> 2,         c0 = tid & 3;
    const int r1 = (tid + 256) >> 2, c1 = (tid + 256) & 3;
    const uint32_t so0 = swz4(r0, c0);
    const uint32_t so1 = swz4(r1, c1);

    auto issue_chunk = [&](int k, int stage) {
        const int kt = k * KC;
        const uint32_t sbA = smem0 + stage * STAGEB;
        const uint32_t sbB = sbA + TILEB;
        cpasync16(sbA + so0, g_h + (size_t)(rowi0 + r0) * DIM + kt + c0 * 8);
        cpasync16(sbA + so1, g_h + (size_t)(rowi0 + r1) * DIM + kt + c1 * 8);
        cpasync16(sbB + so0, g_h + (size_t)(rowj0 + r0) * DIM + kt + c0 * 8);
        cpasync16(sbB + so1, g_h + (size_t)(rowj0 + r1) * DIM + kt + c1 * 8);
        CP_MBAR_ARRIVE(mbar0 + stage * 8);
    };

    for (int s = 0; s < NSTAGE; s++) issue_chunk(s, s);

    float acc[2][8][4];
#pragma unroll
    for (int mi = 0; mi < 2; mi++)
#pragma unroll
        for (int ni = 0; ni < 8; ni++)
#pragma unroll
            for (int k = 0; k < 4; k++) acc[mi][ni][k] = 0.f;

    const int m4 = lane >> 3, ri = lane & 7;

    for (int k = 0; k < NCH; k++) {
        const int st = k % NSTAGE;
        const int ph = (k / NSTAGE) & 1;
        MBAR_WAIT(mbar0 + st * 8, ph);            // data ready

        const uint32_t baseA = smem0 + st * STAGEB;
        const uint32_t baseB = baseA + TILEB;

        // load ALL fragments of this chunk, then release the stage
        uint32_t ah[2][2][4], bh[2][4][4];
#pragma unroll
        for (int kk = 0; kk < 2; kk++) {
#pragma unroll
            for (int mi = 0; mi < 2; mi++) {
                int r = wm * 32 + mi * 16 + (m4 & 1) * 8 + ri;
                int c = kk * 2 + (m4 >> 1);
                ldm_x4(ah[kk][mi], baseA + swz4(r, c));
            }
#pragma unroll
            for (int p4 = 0; p4 < 4; p4++) {
                int r = wn * 64 + p4 * 16 + (m4 >> 1) * 8 + ri;
                int c = kk * 2 + (m4 & 1);
                ldm_x4(bh[kk][p4], baseB + swz4(r, c));
            }
        }
        MBAR_ARRIVE(mbar0 + 48 + st * 8);         // stage free (smem reads done)

#pragma unroll
        for (int kk = 0; kk < 2; kk++)
#pragma unroll
            for (int mi = 0; mi < 2; mi++)
#pragma unroll
                for (int ni = 0; ni < 8; ni++)
                    mma16816(acc[mi][ni], ah[kk][mi], &bh[kk][ni >> 1][(ni & 1) * 2]);

        if (k + NSTAGE < NCH) {
            MBAR_WAIT(mbar0 + 48 + st * 8, ph);   // all warps done reading stage
            issue_chunk(k + NSTAGE, st);
        }
    }

    // ---------------- epilogue: dist + masked max/min reductions -----------
    const int g = lane >> 2, tg = lane & 3;
    const float NEG = -dev_inf(), POS = dev_inf();
    float cmx[16], cmn[16];
#pragma unroll
    for (int s = 0; s < 16; s++) { cmx[s] = NEG; cmn[s] = POS; }

#pragma unroll
    for (int mi = 0; mi < 2; mi++)
#pragma unroll
        for (int h = 0; h < 2; h++) {
            int li = wm * 32 + mi * 16 + h * 8 + g;
            int labi = s_li[li];
            float sqi = s_sqi[li];
            float rmax = NEG, rmin = POS;
#pragma unroll
            for (int ni = 0; ni < 8; ni++)
#pragma unroll
                for (int cc = 0; cc < 2; cc++) {
                    int lj = wn * 64 + ni * 8 + tg * 2 + cc;
                    float d = sqi + s_sqj[lj] - 2.0f * acc[mi][ni][h * 2 + cc];
                    int s = ni * 2 + cc;
                    if (labi == s_lj[lj]) {
                        rmax = fmaxf(rmax, d);
                        cmx[s] = fmaxf(cmx[s], d);
                    } else {
                        rmin = fminf(rmin, d);
                        cmn[s] = fminf(cmn[s], d);
                    }
                }
            rmax = fmaxf(rmax, __shfl_xor_sync(0xffffffffu, rmax, 1));
            rmax = fmaxf(rmax, __shfl_xor_sync(0xffffffffu, rmax, 2));
            rmin = fminf(rmin, __shfl_xor_sync(0xffffffffu, rmin, 1));
            rmin = fminf(rmin, __shfl_xor_sync(0xffffffffu, rmin, 2));
            if (tg == 0) {
                int grow = rowi0 + li;
                atomicMax(&g_pos[grow], f2ord(rmax));
                atomicMin(&g_neg[grow], f2ord(rmin));
            }
        }

    // column reduction (symmetry): lanes sharing tg differ in g (bits 2..4)
    if (bi != bj) {
#pragma unroll
        for (int s = 0; s < 16; s++) {
            float m_ = cmx[s], n_ = cmn[s];
            m_ = fmaxf(m_, __shfl_xor_sync(0xffffffffu, m_, 4));
            m_ = fmaxf(m_, __shfl_xor_sync(0xffffffffu, m_, 8));
            m_ = fmaxf(m_, __shfl_xor_sync(0xffffffffu, m_, 16));
            n_ = fminf(n_, __shfl_xor_sync(0xffffffffu, n_, 4));
            n_ = fminf(n_, __shfl_xor_sync(0xffffffffu, n_, 8));
            n_ = fminf(n_, __shfl_xor_sync(0xffffffffu, n_, 16));
            if (g == 0) {
                int gcol = rowj0 + wn * 64 + (s >> 1) * 8 + tg * 2 + (s & 1);
                atomicMax(&g_pos[gcol], f2ord(m_));
                atomicMin(&g_neg[gcol], f2ord(n_));
            }
        }
    }

    // ---------------- last-block finalize (deterministic) -------------------
    __shared__ unsigned s_last;
    __threadfence();
    __syncthreads();
    if (tid == 0)
        s_last = (atomicAdd(&g_done, 1u) == (unsigned)(NTILES - 1));
    __syncthreads();
    if (s_last) {
        float ts = 0.f, cs = 0.f;
        for (int i = tid; i < N_ROWS; i += 256) {
            float p = ord2f(__ldcg(&g_pos[i]));
            float n = ord2f(__ldcg(&g_neg[i]));
            ts += fmaxf(p - n + MARGIN, 0.0f);
            cs += __ldcg(&g_ce[i]);
        }
#pragma unroll
        for (int o = 16; o; o >>= 1) {
            ts += __shfl_xor_sync(0xffffffffu, ts, o);
            cs += __shfl_xor_sync(0xffffffffu, cs, o);
        }
        if (lane == 0) { shw[warp] = ts; shw[8 + warp] = cs; }
        __syncthreads();
        if (tid == 0) {
            float tt = 0.f, ct = 0.f;
#pragma unroll
            for (int w = 0; w < 8; w++) { tt += shw[w]; ct += shw[8 + w]; }
            out[0] = tt / (float)N_ROWS + ct / (float)N_ROWS;
            g_done = 0;
            __threadfence();
        }
    }
}

// ---------------- entry -----------------------------------------------------
extern "C" void kernel_launch(void* const* d_in, const int* in_sizes, int n_in,
                              void* d_out, int out_size) {
    const float* x   = (const float*)d_in[0];
    const void*  lab = d_in[1];

    cudaFuncSetAttribute(gemm_kernel, cudaFuncAttributeMaxDynamicSharedMemorySize, SMEMDYN);
    prep_kernel<<<N_ROWS, 128>>>(x, lab);
    gemm_kernel<<<NTILES, 256, SMEMDYN>>>((float*)d_out);
}

// round 11
// speedup vs baseline: 2.1250x; 1.0495x over previous
#include <cuda_runtime.h>
#include <cuda_fp16.h>
#include <cstdint>

#define N_ROWS 8192
#define DIM    512
#define BT     64            // 8192/128 tiles per dimension
#define MARGIN 0.35f
#define KC     64            // K elems per smem chunk (128B rows)
#define NCH    (DIM / KC)    // 8
#define TILEB  (128 * KC * 2)       // 16384 per operand tile
#define STAGEB (2 * TILEB)          // A + B = 32768
#define SMEMDYN (2 * STAGEB)        // double buffer = 65536
#define NTILES ((BT * (BT + 1)) / 2)

// ---------------- scratch (device globals; no allocation allowed) ----------
__device__ __align__(16) __half g_h[N_ROWS * DIM];
__device__ float    g_sq[N_ROWS];
__device__ float    g_ce[N_ROWS];
__device__ unsigned g_pos[N_ROWS];
__device__ unsigned g_neg[N_ROWS];
__device__ int      g_lab[N_ROWS];
__device__ unsigned g_done;          // zero-init; finalizer re-zeros for graph replay

// ---------------- float <-> monotone unsigned encoding ---------------------
__device__ __forceinline__ unsigned f2ord(float f) {
    unsigned u = __float_as_uint(f);
    return (u & 0x80000000u) ? ~u : (u | 0x80000000u);
}
__device__ __forceinline__ float ord2f(unsigned u) {
    unsigned b = (u & 0x80000000u) ? (u ^ 0x80000000u) : ~u;
    return __uint_as_float(b);
}
__device__ __forceinline__ float dev_inf() { return __int_as_float(0x7f800000); }

// ---------------- prep: norms, CE, fp16 cast, label detect, init -----------
__global__ void prep_kernel(const float* __restrict__ x, const void* __restrict__ labraw) {
    int row = blockIdx.x;
    int t   = threadIdx.x;          // 128 threads
    const float* xr = x + (size_t)row * DIM;

    // int64 labels in [0,512) -> every odd 32-bit word is zero (per-block vote).
    const int* raw32 = (const int*)labraw;
    int lab64 = !__syncthreads_or(raw32[2 * t + 1] != 0);

    float v[4];
#pragma unroll
    for (int i = 0; i < 4; i++) v[i] = xr[t + 128 * i];

    float ss = 0.f, mx = -dev_inf();
#pragma unroll
    for (int i = 0; i < 4; i++) { ss += v[i] * v[i]; mx = fmaxf(mx, v[i]); }
#pragma unroll
    for (int o = 16; o; o >>= 1) {
        ss += __shfl_xor_sync(0xffffffffu, ss, o);
        mx  = fmaxf(mx, __shfl_xor_sync(0xffffffffu, mx, o));
    }
    __shared__ float s_ss[4], s_mx[4], s_sq[4], s_se[4];
    int w = t >> 5, l = t & 31;
    if (l == 0) { s_ss[w] = ss; s_mx[w] = mx; }
    __syncthreads();
    ss = s_ss[0] + s_ss[1] + s_ss[2] + s_ss[3];
    mx = fmaxf(fmaxf(s_mx[0], s_mx[1]), fmaxf(s_mx[2], s_mx[3]));

    float norm = sqrtf(ss);
    float sq = 0.f, se = 0.f;
#pragma unroll
    for (int i = 0; i < 4; i++) {
        float xn = v[i] / norm;
        sq += xn * xn;
        se += expf(v[i] - mx);
    }
#pragma unroll
    for (int o = 16; o; o >>= 1) {
        sq += __shfl_xor_sync(0xffffffffu, sq, o);
        se += __shfl_xor_sync(0xffffffffu, se, o);
    }
    if (l == 0) { s_sq[w] = sq; s_se[w] = se; }
    __syncthreads();

    if (t == 0) {
        float sqt = s_sq[0] + s_sq[1] + s_sq[2] + s_sq[3];
        float set = s_se[0] + s_se[1] + s_se[2] + s_se[3];
        int lb = lab64 ? (int)((const long long*)labraw)[row]
                       : ((const int*)labraw)[row];
        g_sq[row]  = sqt;
        g_ce[row]  = mx + logf(set) - xr[lb];
        g_lab[row] = lb;
        g_pos[row] = f2ord(-dev_inf());
        g_neg[row] = f2ord(dev_inf());
    }

#pragma unroll
    for (int i = 0; i < 4; i++)
        g_h[(size_t)row * DIM + t + 128 * i] = __float2half_rn(v[i]);
}

// ---------------- mma helpers ----------------------------------------------
__device__ __forceinline__ void ldm_x4(uint32_t* d, uint32_t addr) {
    asm volatile("ldmatrix.sync.aligned.m8n8.x4.shared.b16 {%0,%1,%2,%3}, [%4];\n"
                 : "=r"(d[0]), "=r"(d[1]), "=r"(d[2]), "=r"(d[3]) : "r"(addr));
}
// fp16 accumulators: C fragment packed half2 x2
__device__ __forceinline__ void mma16816h(uint32_t* c, const uint32_t* a, const uint32_t* b) {
    asm volatile(
        "mma.sync.aligned.m16n8k16.row.col.f16.f16.f16.f16 "
        "{%0,%1}, {%2,%3,%4,%5}, {%6,%7}, {%0,%1};\n"
        : "+r"(c[0]), "+r"(c[1])
        : "r"(a[0]), "r"(a[1]), "r"(a[2]), "r"(a[3]), "r"(b[0]), "r"(b[1]));
}
__device__ __forceinline__ void cpasync16(uint32_t dst, const void* src) {
    asm volatile("cp.async.cg.shared.global [%0], [%1], 16;" :: "r"(dst), "l"(src));
}

// swizzled 16B-chunk byte offset for (row r, logical chunk c) in 128x64 fp16 tile
__device__ __forceinline__ uint32_t swz8(int r, int c) {
    return (uint32_t)((r * 8 + (c ^ (r & 7))) << 4);
}

// ---------------- fused triangular GEMM + masked max/min + finalize --------
__global__ void __launch_bounds__(256, 3) gemm_kernel(float* out) {
    extern __shared__ __align__(1024) char smdyn[];
    __shared__ float s_sqi[128], s_sqj[128];
    __shared__ int   s_li[128], s_lj[128];
    __shared__ float shw[16];

    // map linear block -> upper-triangular tile (bi <= bj)
    int b = blockIdx.x;
    int bi = 0;
    while ((bi + 1) * BT - ((bi + 1) * bi) / 2 <= b) bi++;
    int bj = bi + (b - (bi * BT - (bi * (bi - 1)) / 2));

    const int tid  = threadIdx.x;
    const int lane = tid & 31, warp = tid >> 5;
    const int wm = warp & 3, wn = warp >> 2;   // 4x2 warp grid: 32-row x 64-col per warp

    const int rowi0 = bi * 128, rowj0 = bj * 128;
    if (tid < 128) { s_sqi[tid] = g_sq[rowi0 + tid]; s_li[tid] = g_lab[rowi0 + tid]; }
    else { int t2 = tid - 128; s_sqj[t2] = g_sq[rowj0 + t2]; s_lj[t2] = g_lab[rowj0 + t2]; }

    uint32_t acc[2][8][2];
#pragma unroll
    for (int mi = 0; mi < 2; mi++)
#pragma unroll
        for (int ni = 0; ni < 8; ni++) { acc[mi][ni][0] = 0u; acc[mi][ni][1] = 0u; }

    uint32_t smem0;
    asm("{ .reg .u64 t; cvta.to.shared.u64 t, %1; cvt.u32.u64 %0, t; }"
        : "=r"(smem0) : "l"(smdyn));

    auto issue_chunk = [&](int k, int stage) {
        const int kt = k * KC;
        const uint32_t sbA = smem0 + stage * STAGEB;
        const uint32_t sbB = sbA + TILEB;
#pragma unroll
        for (int rep = 0; rep < 4; rep++) {
            int q = rep * 256 + tid;            // 0..1023
            int r = q >> 3, c = q & 7;
            uint32_t so = swz8(r, c);
            size_t ga = (size_t)(rowi0 + r) * DIM + kt + c * 8;
            size_t gb = (size_t)(rowj0 + r) * DIM + kt + c * 8;
            cpasync16(sbA + so, g_h + ga);
            cpasync16(sbB + so, g_h + gb);
        }
        asm volatile("cp.async.commit_group;" ::: "memory");
    };

    issue_chunk(0, 0);

    const int m4 = lane >> 3, ri = lane & 7;

    for (int k = 0; k < NCH; k++) {
        if (k + 1 < NCH) {
            issue_chunk(k + 1, (k + 1) & 1);
            asm volatile("cp.async.wait_group 1;" ::: "memory");
        } else {
            asm volatile("cp.async.wait_group 0;" ::: "memory");
        }
        __syncthreads();

        const uint32_t baseA = smem0 + (k & 1) * STAGEB;
        const uint32_t baseB = baseA + TILEB;

#pragma unroll
        for (int kk = 0; kk < 4; kk++) {
            uint32_t ah[2][4];
#pragma unroll
            for (int mi = 0; mi < 2; mi++) {
                int r = wm * 32 + mi * 16 + (m4 & 1) * 8 + ri;
                int c = kk * 2 + (m4 >> 1);
                ldm_x4(ah[mi], baseA + swz8(r, c));
            }
            uint32_t bh[4][4];
#pragma unroll
            for (int p4 = 0; p4 < 4; p4++) {
                int r = wn * 64 + p4 * 16 + (m4 >> 1) * 8 + ri;
                int c = kk * 2 + (m4 & 1);
                ldm_x4(bh[p4], baseB + swz8(r, c));
            }
#pragma unroll
            for (int mi = 0; mi < 2; mi++)
#pragma unroll
                for (int ni = 0; ni < 8; ni++)
                    mma16816h(acc[mi][ni], ah[mi], &bh[ni >> 1][(ni & 1) * 2]);
        }
        __syncthreads();
    }

    // ---------------- epilogue: dist + masked max/min reductions -----------
    const int g = lane >> 2, tg = lane & 3;
    const float NEG = -dev_inf(), POS = dev_inf();
    float cmx[16], cmn[16];
#pragma unroll
    for (int s = 0; s < 16; s++) { cmx[s] = NEG; cmn[s] = POS; }

#pragma unroll
    for (int mi = 0; mi < 2; mi++)
#pragma unroll
        for (int h = 0; h < 2; h++) {
            int li = wm * 32 + mi * 16 + h * 8 + g;
            int labi = s_li[li];
            float sqi = s_sqi[li];
            float rmax = NEG, rmin = POS;
#pragma unroll
            for (int ni = 0; ni < 8; ni++) {
                float2 f = __half22float2(*reinterpret_cast<__half2*>(&acc[mi][ni][h]));
#pragma unroll
                for (int cc = 0; cc < 2; cc++) {
                    int lj = wn * 64 + ni * 8 + tg * 2 + cc;
                    float d = sqi + s_sqj[lj] - 2.0f * (cc ? f.y : f.x);
                    int s = ni * 2 + cc;
                    if (labi == s_lj[lj]) {
                        rmax = fmaxf(rmax, d);
                        cmx[s] = fmaxf(cmx[s], d);
                    } else {
                        rmin = fminf(rmin, d);
                        cmn[s] = fminf(cmn[s], d);
                    }
                }
            }
            // row reduction across tg (low 2 lane bits)
            rmax = fmaxf(rmax, __shfl_xor_sync(0xffffffffu, rmax, 1));
            rmax = fmaxf(rmax, __shfl_xor_sync(0xffffffffu, rmax, 2));
            rmin = fminf(rmin, __shfl_xor_sync(0xffffffffu, rmin, 1));
            rmin = fminf(rmin, __shfl_xor_sync(0xffffffffu, rmin, 2));
            if (tg == 0) {
                int grow = rowi0 + li;
                atomicMax(&g_pos[grow], f2ord(rmax));
                atomicMin(&g_neg[grow], f2ord(rmin));
            }
        }

    // column reduction (symmetry): lanes sharing tg differ in g (bits 2..4)
    if (bi != bj) {
#pragma unroll
        for (int s = 0; s < 16; s++) {
            float m_ = cmx[s], n_ = cmn[s];
            m_ = fmaxf(m_, __shfl_xor_sync(0xffffffffu, m_, 4));
            m_ = fmaxf(m_, __shfl_xor_sync(0xffffffffu, m_, 8));
            m_ = fmaxf(m_, __shfl_xor_sync(0xffffffffu, m_, 16));
            n_ = fminf(n_, __shfl_xor_sync(0xffffffffu, n_, 4));
            n_ = fminf(n_, __shfl_xor_sync(0xffffffffu, n_, 8));
            n_ = fminf(n_, __shfl_xor_sync(0xffffffffu, n_, 16));
            if (g == 0) {
                int gcol = rowj0 + wn * 64 + (s >> 1) * 8 + tg * 2 + (s & 1);
                atomicMax(&g_pos[gcol], f2ord(m_));
                atomicMin(&g_neg[gcol], f2ord(n_));
            }
        }
    }

    // ---------------- last-block finalize (deterministic) -------------------
    __shared__ unsigned s_last;
    __threadfence();
    __syncthreads();
    if (tid == 0)
        s_last = (atomicAdd(&g_done, 1u) == (unsigned)(NTILES - 1));
    __syncthreads();
    if (s_last) {
        float ts = 0.f, cs = 0.f;
        for (int i = tid; i < N_ROWS; i += 256) {
            float p = ord2f(__ldcg(&g_pos[i]));
            float n = ord2f(__ldcg(&g_neg[i]));
            ts += fmaxf(p - n + MARGIN, 0.0f);
            cs += __ldcg(&g_ce[i]);
        }
#pragma unroll
        for (int o = 16; o; o >>= 1) {
            ts += __shfl_xor_sync(0xffffffffu, ts, o);
            cs += __shfl_xor_sync(0xffffffffu, cs, o);
        }
        if (lane == 0) { shw[warp] = ts; shw[8 + warp] = cs; }
        __syncthreads();
        if (tid == 0) {
            float tt = 0.f, ct = 0.f;
#pragma unroll
            for (int w = 0; w < 8; w++) { tt += shw[w]; ct += shw[8 + w]; }
            out[0] = tt / (float)N_ROWS + ct / (float)N_ROWS;
            g_done = 0;
            __threadfence();
        }
    }
}

// ---------------- entry -----------------------------------------------------
extern "C" void kernel_launch(void* const* d_in, const int* in_sizes, int n_in,
                              void* d_out, int out_size) {
    const float* x   = (const float*)d_in[0];
    const void*  lab = d_in[1];

    cudaFuncSetAttribute(gemm_kernel, cudaFuncAttributeMaxDynamicSharedMemorySize, SMEMDYN);
    prep_kernel<<<N_ROWS, 128>>>(x, lab);
    gemm_kernel<<<NTILES, 256, SMEMDYN>>>((float*)d_out);
}

// round 12
// speedup vs baseline: 2.2915x; 1.0783x over previous
#include <cuda_runtime.h>
#include <cuda_fp16.h>
#include <cstdint>

#define N_ROWS 8192
#define DIM    512
#define MARGIN 0.35f
#define KC     64                    // K elems per smem chunk (128B rows)
#define NCH    (DIM / KC)            // 8
#define TM     128                   // CTA tile rows (A)
#define TN     256                   // CTA tile cols (B)
#define ATILEB (TM * KC * 2)         // 16384
#define BTILEB (TN * KC * 2)         // 32768
#define STAGEB (ATILEB + BTILEB)     // 49152
#define SMEMDYN (2 * STAGEB)         // 98304 (double buffer)
#define NTILES 1056                  // {(bi,bj): 0<=bi<64, floor(bi/2)<=bj<32}

// ---------------- scratch (device globals; no allocation allowed) ----------
__device__ __align__(16) __half g_h[N_ROWS * DIM];
__device__ float    g_sq[N_ROWS];
__device__ float    g_ce[N_ROWS];
__device__ unsigned g_pos[N_ROWS];
__device__ unsigned g_neg[N_ROWS];
__device__ int      g_lab[N_ROWS];
__device__ unsigned g_done;          // zero-init; finalizer re-zeros for graph replay

// ---------------- float <-> monotone unsigned encoding ---------------------
__device__ __forceinline__ unsigned f2ord(float f) {
    unsigned u = __float_as_uint(f);
    return (u & 0x80000000u) ? ~u : (u | 0x80000000u);
}
__device__ __forceinline__ float ord2f(unsigned u) {
    unsigned b = (u & 0x80000000u) ? (u ^ 0x80000000u) : ~u;
    return __uint_as_float(b);
}
__device__ __forceinline__ float dev_inf() { return __int_as_float(0x7f800000); }

// ---------------- prep: norms, CE, fp16 cast, label detect, init -----------
__global__ void prep_kernel(const float* __restrict__ x, const void* __restrict__ labraw) {
    int row = blockIdx.x;
    int t   = threadIdx.x;          // 128 threads
    const float* xr = x + (size_t)row * DIM;

    // int64 labels in [0,512) -> every odd 32-bit word is zero (per-block vote).
    const int* raw32 = (const int*)labraw;
    int lab64 = !__syncthreads_or(raw32[2 * t + 1] != 0);

    float v[4];
#pragma unroll
    for (int i = 0; i < 4; i++) v[i] = xr[t + 128 * i];

    float ss = 0.f, mx = -dev_inf();
#pragma unroll
    for (int i = 0; i < 4; i++) { ss += v[i] * v[i]; mx = fmaxf(mx, v[i]); }
#pragma unroll
    for (int o = 16; o; o >>= 1) {
        ss += __shfl_xor_sync(0xffffffffu, ss, o);
        mx  = fmaxf(mx, __shfl_xor_sync(0xffffffffu, mx, o));
    }
    __shared__ float s_ss[4], s_mx[4], s_sq[4], s_se[4];
    int w = t >> 5, l = t & 31;
    if (l == 0) { s_ss[w] = ss; s_mx[w] = mx; }
    __syncthreads();
    ss = s_ss[0] + s_ss[1] + s_ss[2] + s_ss[3];
    mx = fmaxf(fmaxf(s_mx[0], s_mx[1]), fmaxf(s_mx[2], s_mx[3]));

    float norm = sqrtf(ss);
    float sq = 0.f, se = 0.f;
#pragma unroll
    for (int i = 0; i < 4; i++) {
        float xn = v[i] / norm;
        sq += xn * xn;
        se += expf(v[i] - mx);
    }
#pragma unroll
    for (int o = 16; o; o >>= 1) {
        sq += __shfl_xor_sync(0xffffffffu, sq, o);
        se += __shfl_xor_sync(0xffffffffu, se, o);
    }
    if (l == 0) { s_sq[w] = sq; s_se[w] = se; }
    __syncthreads();

    if (t == 0) {
        float sqt = s_sq[0] + s_sq[1] + s_sq[2] + s_sq[3];
        float set = s_se[0] + s_se[1] + s_se[2] + s_se[3];
        int lb = lab64 ? (int)((const long long*)labraw)[row]
                       : ((const int*)labraw)[row];
        g_sq[row]  = sqt;
        g_ce[row]  = mx + logf(set) - xr[lb];
        g_lab[row] = lb;
        g_pos[row] = f2ord(-dev_inf());
        g_neg[row] = f2ord(dev_inf());
    }

#pragma unroll
    for (int i = 0; i < 4; i++)
        g_h[(size_t)row * DIM + t + 128 * i] = __float2half_rn(v[i]);
}

// ---------------- mma helpers ----------------------------------------------
__device__ __forceinline__ void ldm_x4(uint32_t* d, uint32_t addr) {
    asm volatile("ldmatrix.sync.aligned.m8n8.x4.shared.b16 {%0,%1,%2,%3}, [%4];\n"
                 : "=r"(d[0]), "=r"(d[1]), "=r"(d[2]), "=r"(d[3]) : "r"(addr));
}
// fp16 accumulators: C fragment packed half2 x2
__device__ __forceinline__ void mma16816h(uint32_t* c, const uint32_t* a, const uint32_t* b) {
    asm volatile(
        "mma.sync.aligned.m16n8k16.row.col.f16.f16.f16.f16 "
        "{%0,%1}, {%2,%3,%4,%5}, {%6,%7}, {%0,%1};\n"
        : "+r"(c[0]), "+r"(c[1])
        : "r"(a[0]), "r"(a[1]), "r"(a[2]), "r"(a[3]), "r"(b[0]), "r"(b[1]));
}
__device__ __forceinline__ void cpasync16(uint32_t dst, const void* src) {
    asm volatile("cp.async.cg.shared.global [%0], [%1], 16;" :: "r"(dst), "l"(src));
}

// swizzled 16B-chunk byte offset for (row r, logical chunk c), 128B rows
__device__ __forceinline__ uint32_t swz8(int r, int c) {
    return (uint32_t)((r * 8 + (c ^ (r & 7))) << 4);
}

// ---------------- fused triangular GEMM + masked max/min + finalize --------
__global__ void __launch_bounds__(256, 2) gemm_kernel(float* out) {
    extern __shared__ __align__(1024) char smdyn[];
    __shared__ float s_sqi[TM], s_sqj[TN];
    __shared__ int   s_li[TM], s_lj[TN];
    __shared__ float shw[16];

    // map linear block -> tile (bi in 128-row units, bj in 256-col units, bj >= bi/2)
    // cum(2m) = 64m - m(m-1); cum(2m+1) = 64m + 32 - m^2
    int b = blockIdx.x;
    int bi = 0;
    for (;;) {
        int t = bi + 1, m = t >> 1;
        int cumn = (t & 1) ? (64 * m + 32 - m * m) : (64 * m - m * (m - 1));
        if (cumn > b) break;
        bi++;
    }
    int m0 = bi >> 1;
    int cumb = (bi & 1) ? (64 * m0 + 32 - m0 * m0) : (64 * m0 - m0 * (m0 - 1));
    int bj = (bi >> 1) + (b - cumb);

    const int tid  = threadIdx.x;
    const int lane = tid & 31, warp = tid >> 5;
    const int wm = warp & 1, wn = warp >> 1;   // 2x4 warp grid: 64-row x 64-col per warp

    const int rowi0 = bi * TM, rowj0 = bj * TN;
    if (tid < TM) { s_sqi[tid] = g_sq[rowi0 + tid]; s_li[tid] = g_lab[rowi0 + tid]; }
    s_sqj[tid] = g_sq[rowj0 + tid];
    s_lj[tid]  = g_lab[rowj0 + tid];

    uint32_t acc[4][8][2];
#pragma unroll
    for (int mi = 0; mi < 4; mi++)
#pragma unroll
        for (int ni = 0; ni < 8; ni++) { acc[mi][ni][0] = 0u; acc[mi][ni][1] = 0u; }

    uint32_t smem0;
    asm("{ .reg .u64 t; cvta.to.shared.u64 t, %1; cvt.u32.u64 %0, t; }"
        : "=r"(smem0) : "l"(smdyn));

    auto issue_chunk = [&](int k, int stage) {
        const int kt = k * KC;
        const uint32_t sbA = smem0 + stage * STAGEB;
        const uint32_t sbB = sbA + ATILEB;
#pragma unroll
        for (int rep = 0; rep < 4; rep++) {           // A: 128 rows x 8 chunks
            int q = rep * 256 + tid;
            int r = q >> 3, c = q & 7;
            cpasync16(sbA + swz8(r, c), g_h + (size_t)(rowi0 + r) * DIM + kt + c * 8);
        }
#pragma unroll
        for (int rep = 0; rep < 8; rep++) {           // B: 256 rows x 8 chunks
            int q = rep * 256 + tid;
            int r = q >> 3, c = q & 7;
            cpasync16(sbB + swz8(r, c), g_h + (size_t)(rowj0 + r) * DIM + kt + c * 8);
        }
        asm volatile("cp.async.commit_group;" ::: "memory");
    };

    issue_chunk(0, 0);

    const int m4 = lane >> 3, ri = lane & 7;

    for (int k = 0; k < NCH; k++) {
        if (k + 1 < NCH) {
            issue_chunk(k + 1, (k + 1) & 1);
            asm volatile("cp.async.wait_group 1;" ::: "memory");
        } else {
            asm volatile("cp.async.wait_group 0;" ::: "memory");
        }
        __syncthreads();

        const uint32_t baseA = smem0 + (k & 1) * STAGEB;
        const uint32_t baseB = baseA + ATILEB;

#pragma unroll
        for (int kk = 0; kk < 4; kk++) {
            uint32_t ah[4][4];
#pragma unroll
            for (int mi = 0; mi < 4; mi++) {
                int r = wm * 64 + mi * 16 + (m4 & 1) * 8 + ri;
                int c = kk * 2 + (m4 >> 1);
                ldm_x4(ah[mi], baseA + swz8(r, c));
            }
            uint32_t bh[4][4];
#pragma unroll
            for (int p4 = 0; p4 < 4; p4++) {
                int r = wn * 64 + p4 * 16 + (m4 >> 1) * 8 + ri;
                int c = kk * 2 + (m4 & 1);
                ldm_x4(bh[p4], baseB + swz8(r, c));
            }
#pragma unroll
            for (int mi = 0; mi < 4; mi++)
#pragma unroll
                for (int ni = 0; ni < 8; ni++)
                    mma16816h(acc[mi][ni], ah[mi], &bh[ni >> 1][(ni & 1) * 2]);
        }
        __syncthreads();
    }

    // ---------------- epilogue: dist + masked max/min reductions -----------
    const int g = lane >> 2, tg = lane & 3;
    const float NEG = -dev_inf(), POS = dev_inf();
    float cmx[16], cmn[16];
#pragma unroll
    for (int s = 0; s < 16; s++) { cmx[s] = NEG; cmn[s] = POS; }

#pragma unroll
    for (int mi = 0; mi < 4; mi++)
#pragma unroll
        for (int h = 0; h < 2; h++) {
            int li = wm * 64 + mi * 16 + h * 8 + g;
            int labi = s_li[li];
            float sqi = s_sqi[li];
            float rmax = NEG, rmin = POS;
#pragma unroll
            for (int ni = 0; ni < 8; ni++) {
                float2 f = __half22float2(*reinterpret_cast<__half2*>(&acc[mi][ni][h]));
#pragma unroll
                for (int cc = 0; cc < 2; cc++) {
                    int lj = wn * 64 + ni * 8 + tg * 2 + cc;
                    float d = sqi + s_sqj[lj] - 2.0f * (cc ? f.y : f.x);
                    int s = ni * 2 + cc;
                    if (labi == s_lj[lj]) {
                        rmax = fmaxf(rmax, d);
                        cmx[s] = fmaxf(cmx[s], d);
                    } else {
                        rmin = fminf(rmin, d);
                        cmn[s] = fminf(cmn[s], d);
                    }
                }
            }
            // row reduction across tg (low 2 lane bits)
            rmax = fmaxf(rmax, __shfl_xor_sync(0xffffffffu, rmax, 1));
            rmax = fmaxf(rmax, __shfl_xor_sync(0xffffffffu, rmax, 2));
            rmin = fminf(rmin, __shfl_xor_sync(0xffffffffu, rmin, 1));
            rmin = fminf(rmin, __shfl_xor_sync(0xffffffffu, rmin, 2));
            if (tg == 0) {
                int grow = rowi0 + li;
                atomicMax(&g_pos[grow], f2ord(rmax));
                atomicMin(&g_neg[grow], f2ord(rmin));
            }
        }

    // column-side reduction (always; symmetric dist values are idempotent)
#pragma unroll
    for (int s = 0; s < 16; s++) {
        float m_ = cmx[s], n_ = cmn[s];
        m_ = fmaxf(m_, __shfl_xor_sync(0xffffffffu, m_, 4));
        m_ = fmaxf(m_, __shfl_xor_sync(0xffffffffu, m_, 8));
        m_ = fmaxf(m_, __shfl_xor_sync(0xffffffffu, m_, 16));
        n_ = fminf(n_, __shfl_xor_sync(0xffffffffu, n_, 4));
        n_ = fminf(n_, __shfl_xor_sync(0xffffffffu, n_, 8));
        n_ = fminf(n_, __shfl_xor_sync(0xffffffffu, n_, 16));
        if (g == 0) {
            int gcol = rowj0 + wn * 64 + (s >> 1) * 8 + tg * 2 + (s & 1);
            atomicMax(&g_pos[gcol], f2ord(m_));
            atomicMin(&g_neg[gcol], f2ord(n_));
        }
    }

    // ---------------- last-block finalize (deterministic) -------------------
    __shared__ unsigned s_last;
    __threadfence();
    __syncthreads();
    if (tid == 0)
        s_last = (atomicAdd(&g_done, 1u) == (unsigned)(NTILES - 1));
    __syncthreads();
    if (s_last) {
        float ts = 0.f, cs = 0.f;
        for (int i = tid; i < N_ROWS; i += 256) {
            float p = ord2f(__ldcg(&g_pos[i]));
            float n = ord2f(__ldcg(&g_neg[i]));
            ts += fmaxf(p - n + MARGIN, 0.0f);
            cs += __ldcg(&g_ce[i]);
        }
#pragma unroll
        for (int o = 16; o; o >>= 1) {
            ts += __shfl_xor_sync(0xffffffffu, ts, o);
            cs += __shfl_xor_sync(0xffffffffu, cs, o);
        }
        if (lane == 0) { shw[warp] = ts; shw[8 + warp] = cs; }
        __syncthreads();
        if (tid == 0) {
            float tt = 0.f, ct = 0.f;
#pragma unroll
            for (int w = 0; w < 8; w++) { tt += shw[w]; ct += shw[8 + w]; }
            out[0] = tt / (float)N_ROWS + ct / (float)N_ROWS;
            g_done = 0;
            __threadfence();
        }
    }
}

// ---------------- entry -----------------------------------------------------
extern "C" void kernel_launch(void* const* d_in, const int* in_sizes, int n_in,
                              void* d_out, int out_size) {
    const float* x   = (const float*)d_in[0];
    const void*  lab = d_in[1];

    cudaFuncSetAttribute(gemm_kernel, cudaFuncAttributeMaxDynamicSharedMemorySize, SMEMDYN);
    prep_kernel<<<N_ROWS, 128>>>(x, lab);
    gemm_kernel<<<NTILES, 256, SMEMDYN>>>((float*)d_out);
}

// round 13
// speedup vs baseline: 2.4553x; 1.0715x over previous
#include <cuda_runtime.h>
#include <cuda_fp16.h>
#include <cstdint>

#define N_ROWS 8192
#define DIM    512
#define MARGIN 0.35f
#define KC     64                    // K elems per smem chunk (128B rows)
#define NCH    (DIM / KC)            // 8
#define TM     128                   // CTA tile rows (A)
#define TN     256                   // CTA tile cols (B)
#define ATILEB (TM * KC * 2)         // 16384
#define BTILEB (TN * KC * 2)         // 32768
#define STAGEB (ATILEB + BTILEB)     // 49152
#define SMEMDYN (2 * STAGEB)         // 98304 (double buffer)
#define NTILES 1056                  // {(bi,bj): 0<=bi<64, floor(bi/2)<=bj<32}

// ---------------- scratch (device globals; no allocation allowed) ----------
__device__ __align__(16) __half g_h[N_ROWS * DIM];
__device__ float    g_sq[N_ROWS];
__device__ float    g_ce[N_ROWS];
__device__ unsigned g_pos[N_ROWS];
__device__ unsigned g_neg[N_ROWS];
__device__ int      g_lab[N_ROWS];
__device__ unsigned g_done;          // zero-init; finalizer re-zeros for graph replay

// ---------------- float <-> monotone unsigned encoding ---------------------
__device__ __forceinline__ unsigned f2ord(float f) {
    unsigned u = __float_as_uint(f);
    return (u & 0x80000000u) ? ~u : (u | 0x80000000u);
}
__device__ __forceinline__ float ord2f(unsigned u) {
    unsigned b = (u & 0x80000000u) ? (u ^ 0x80000000u) : ~u;
    return __uint_as_float(b);
}
__device__ __forceinline__ float dev_inf() { return __int_as_float(0x7f800000); }

// ---------------- mbarrier helpers ------------------------------------------
#define MBAR_INIT(a, c) \
    asm volatile("mbarrier.init.shared.b64 [%0], %1;" :: "r"((uint32_t)(a)), "r"((uint32_t)(c)) : "memory")
#define MBAR_ARRIVE(a) \
    asm volatile("mbarrier.arrive.shared.b64 _, [%0];" :: "r"((uint32_t)(a)) : "memory")
#define CP_MBAR_ARRIVE(a) \
    asm volatile("cp.async.mbarrier.arrive.noinc.shared.b64 [%0];" :: "r"((uint32_t)(a)) : "memory")
#define MBAR_WAIT(a, ph) do {                                                          \
    uint32_t _m = (uint32_t)(a), _p = (uint32_t)(ph), _d;                              \
    asm volatile("{ .reg .pred p; mbarrier.try_wait.parity.acquire.cta.shared::cta.b64 p, [%1], %2;" \
                 " selp.b32 %0, 1, 0, p; }" : "=r"(_d) : "r"(_m), "r"(_p) : "memory"); \
    if (!_d) {                                                                         \
        asm volatile("{ .reg .pred P1; WL_%=: mbarrier.try_wait.parity.acquire.cta.shared::cta.b64 P1, [%0], %1, 0x989680;" \
                     " @P1 bra.uni WD_%=; bra.uni WL_%=; WD_%=: }" :: "r"(_m), "r"(_p) : "memory"); \
    } } while (0)

// ---------------- prep: norms, CE, fp16 cast, label detect, init -----------
__global__ void prep_kernel(const float* __restrict__ x, const void* __restrict__ labraw) {
    int row = blockIdx.x;
    int t   = threadIdx.x;          // 128 threads
    const float* xr = x + (size_t)row * DIM;

    // int64 labels in [0,512) -> every odd 32-bit word is zero (per-block vote).
    const int* raw32 = (const int*)labraw;
    int lab64 = !__syncthreads_or(raw32[2 * t + 1] != 0);

    float v[4];
#pragma unroll
    for (int i = 0; i < 4; i++) v[i] = xr[t + 128 * i];

    float ss = 0.f, mx = -dev_inf();
#pragma unroll
    for (int i = 0; i < 4; i++) { ss += v[i] * v[i]; mx = fmaxf(mx, v[i]); }
#pragma unroll
    for (int o = 16; o; o >>= 1) {
        ss += __shfl_xor_sync(0xffffffffu, ss, o);
        mx  = fmaxf(mx, __shfl_xor_sync(0xffffffffu, mx, o));
    }
    __shared__ float s_ss[4], s_mx[4], s_sq[4], s_se[4];
    int w = t >> 5, l = t & 31;
    if (l == 0) { s_ss[w] = ss; s_mx[w] = mx; }
    __syncthreads();
    ss = s_ss[0] + s_ss[1] + s_ss[2] + s_ss[3];
    mx = fmaxf(fmaxf(s_mx[0], s_mx[1]), fmaxf(s_mx[2], s_mx[3]));

    float norm = sqrtf(ss);
    float sq = 0.f, se = 0.f;
#pragma unroll
    for (int i = 0; i < 4; i++) {
        float xn = v[i] / norm;
        sq += xn * xn;
        se += expf(v[i] - mx);
    }
#pragma unroll
    for (int o = 16; o; o >>= 1) {
        sq += __shfl_xor_sync(0xffffffffu, sq, o);
        se += __shfl_xor_sync(0xffffffffu, se, o);
    }
    if (l == 0) { s_sq[w] = sq; s_se[w] = se; }
    __syncthreads();

    if (t == 0) {
        float sqt = s_sq[0] + s_sq[1] + s_sq[2] + s_sq[3];
        float set = s_se[0] + s_se[1] + s_se[2] + s_se[3];
        int lb = lab64 ? (int)((const long long*)labraw)[row]
                       : ((const int*)labraw)[row];
        g_sq[row]  = sqt;
        g_ce[row]  = mx + logf(set) - xr[lb];
        g_lab[row] = lb;
        g_pos[row] = f2ord(-dev_inf());
        g_neg[row] = f2ord(dev_inf());
    }

#pragma unroll
    for (int i = 0; i < 4; i++)
        g_h[(size_t)row * DIM + t + 128 * i] = __float2half_rn(v[i]);
}

// ---------------- mma helpers ----------------------------------------------
__device__ __forceinline__ void ldm_x4(uint32_t* d, uint32_t addr) {
    asm volatile("ldmatrix.sync.aligned.m8n8.x4.shared.b16 {%0,%1,%2,%3}, [%4];\n"
                 : "=r"(d[0]), "=r"(d[1]), "=r"(d[2]), "=r"(d[3]) : "r"(addr));
}
// fp16 accumulators: C fragment packed half2 x2
__device__ __forceinline__ void mma16816h(uint32_t* c, const uint32_t* a, const uint32_t* b) {
    asm volatile(
        "mma.sync.aligned.m16n8k16.row.col.f16.f16.f16.f16 "
        "{%0,%1}, {%2,%3,%4,%5}, {%6,%7}, {%0,%1};\n"
        : "+r"(c[0]), "+r"(c[1])
        : "r"(a[0]), "r"(a[1]), "r"(a[2]), "r"(a[3]), "r"(b[0]), "r"(b[1]));
}
__device__ __forceinline__ void cpasync16(uint32_t dst, const void* src) {
    asm volatile("cp.async.cg.shared.global [%0], [%1], 16;" :: "r"(dst), "l"(src));
}

// swizzled 16B-chunk byte offset for (row r, logical chunk c), 128B rows
__device__ __forceinline__ uint32_t swz8(int r, int c) {
    return (uint32_t)((r * 8 + (c ^ (r & 7))) << 4);
}

// ---------------- fused triangular GEMM + masked max/min + finalize --------
__global__ void __launch_bounds__(256, 2) gemm_kernel(float* out) {
    extern __shared__ __align__(1024) char smdyn[];
    __shared__ __align__(8) unsigned long long s_mbar[4]; // full[2], empty[2]
    __shared__ float s_sqi[TM], s_sqj[TN];
    __shared__ int   s_li[TM], s_lj[TN];
    __shared__ float shw[16];

    // map linear block -> tile (bi in 128-row units, bj in 256-col units, bj >= bi/2)
    int b = blockIdx.x;
    int bi = 0;
    for (;;) {
        int t = bi + 1, m = t >> 1;
        int cumn = (t & 1) ? (64 * m + 32 - m * m) : (64 * m - m * (m - 1));
        if (cumn > b) break;
        bi++;
    }
    int m0 = bi >> 1;
    int cumb = (bi & 1) ? (64 * m0 + 32 - m0 * m0) : (64 * m0 - m0 * (m0 - 1));
    int bj = (bi >> 1) + (b - cumb);

    const int tid  = threadIdx.x;
    const int lane = tid & 31, warp = tid >> 5;
    const int wm = warp & 1, wn = warp >> 1;   // 2x4 warp grid: 64-row x 64-col per warp

    const int rowi0 = bi * TM, rowj0 = bj * TN;

    uint32_t smem0, mbar0;
    asm("{ .reg .u64 t; cvta.to.shared.u64 t, %1; cvt.u32.u64 %0, t; }"
        : "=r"(smem0) : "l"(smdyn));
    asm("{ .reg .u64 t; cvta.to.shared.u64 t, %1; cvt.u32.u64 %0, t; }"
        : "=r"(mbar0) : "l"(s_mbar));
    // full[s] = mbar0 + s*8 ; empty[s] = mbar0 + 16 + s*8

    if (tid == 0) {
#pragma unroll
        for (int s = 0; s < 2; s++) {
            MBAR_INIT(mbar0 + s * 8, 256);        // full: 256 cp-async arrives
            MBAR_INIT(mbar0 + 16 + s * 8, 256);   // empty: 256 thread arrives
        }
    }
    if (tid < TM) { s_sqi[tid] = g_sq[rowi0 + tid]; s_li[tid] = g_lab[rowi0 + tid]; }
    s_sqj[tid] = g_sq[rowj0 + tid];
    s_lj[tid]  = g_lab[rowj0 + tid];
    __syncthreads();                              // mbarriers + metadata visible

    auto issue_chunk = [&](int k, int stage) {
        const int kt = k * KC;
        const uint32_t sbA = smem0 + stage * STAGEB;
        const uint32_t sbB = sbA + ATILEB;
#pragma unroll
        for (int rep = 0; rep < 4; rep++) {           // A: 128 rows x 8 chunks
            int q = rep * 256 + tid;
            int r = q >> 3, c = q & 7;
            cpasync16(sbA + swz8(r, c), g_h + (size_t)(rowi0 + r) * DIM + kt + c * 8);
        }
#pragma unroll
        for (int rep = 0; rep < 8; rep++) {           // B: 256 rows x 8 chunks
            int q = rep * 256 + tid;
            int r = q >> 3, c = q & 7;
            cpasync16(sbB + swz8(r, c), g_h + (size_t)(rowj0 + r) * DIM + kt + c * 8);
        }
        CP_MBAR_ARRIVE(mbar0 + stage * 8);
    };

    issue_chunk(0, 0);
    issue_chunk(1, 1);

    uint32_t acc[4][8][2];
#pragma unroll
    for (int mi = 0; mi < 4; mi++)
#pragma unroll
        for (int ni = 0; ni < 8; ni++) { acc[mi][ni][0] = 0u; acc[mi][ni][1] = 0u; }

    const int m4 = lane >> 3, ri = lane & 7;

    for (int k = 0; k < NCH; k++) {
        const int st = k & 1;
        const int ph = (k >> 1) & 1;
        MBAR_WAIT(mbar0 + st * 8, ph);            // chunk k data ready

        const uint32_t baseA = smem0 + st * STAGEB;
        const uint32_t baseB = baseA + ATILEB;

#pragma unroll
        for (int kk = 0; kk < 4; kk++) {
            uint32_t ah[4][4];
#pragma unroll
            for (int mi = 0; mi < 4; mi++) {
                int r = wm * 64 + mi * 16 + (m4 & 1) * 8 + ri;
                int c = kk * 2 + (m4 >> 1);
                ldm_x4(ah[mi], baseA + swz8(r, c));
            }
            uint32_t bh[4][4];
#pragma unroll
            for (int p4 = 0; p4 < 4; p4++) {
                int r = wn * 64 + p4 * 16 + (m4 >> 1) * 8 + ri;
                int c = kk * 2 + (m4 & 1);
                ldm_x4(bh[p4], baseB + swz8(r, c));
            }
#pragma unroll
            for (int mi = 0; mi < 4; mi++)
#pragma unroll
                for (int ni = 0; ni < 8; ni++)
                    mma16816h(acc[mi][ni], ah[mi], &bh[ni >> 1][(ni & 1) * 2]);
        }

        MBAR_ARRIVE(mbar0 + 16 + st * 8);         // done reading stage st

        if (k + 2 < NCH) {
            MBAR_WAIT(mbar0 + 16 + st * 8, ph);   // all warps done with stage st
            issue_chunk(k + 2, st);               // refill; used a full chunk later
        }
    }

    // ---------------- epilogue: dist + masked max/min reductions -----------
    const int g = lane >> 2, tg = lane & 3;
    const float NEG = -dev_inf(), POS = dev_inf();
    float cmx[16], cmn[16];
#pragma unroll
    for (int s = 0; s < 16; s++) { cmx[s] = NEG; cmn[s] = POS; }

#pragma unroll
    for (int mi = 0; mi < 4; mi++)
#pragma unroll
        for (int h = 0; h < 2; h++) {
            int li = wm * 64 + mi * 16 + h * 8 + g;
            int labi = s_li[li];
            float sqi = s_sqi[li];
            float rmax = NEG, rmin = POS;
#pragma unroll
            for (int ni = 0; ni < 8; ni++) {
                float2 f = __half22float2(*reinterpret_cast<__half2*>(&acc[mi][ni][h]));
#pragma unroll
                for (int cc = 0; cc < 2; cc++) {
                    int lj = wn * 64 + ni * 8 + tg * 2 + cc;
                    float d = sqi + s_sqj[lj] - 2.0f * (cc ? f.y : f.x);
                    int s = ni * 2 + cc;
                    if (labi == s_lj[lj]) {
                        rmax = fmaxf(rmax, d);
                        cmx[s] = fmaxf(cmx[s], d);
                    } else {
                        rmin = fminf(rmin, d);
                        cmn[s] = fminf(cmn[s], d);
                    }
                }
            }
            // row reduction across tg (low 2 lane bits)
            rmax = fmaxf(rmax, __shfl_xor_sync(0xffffffffu, rmax, 1));
            rmax = fmaxf(rmax, __shfl_xor_sync(0xffffffffu, rmax, 2));
            rmin = fminf(rmin, __shfl_xor_sync(0xffffffffu, rmin, 1));
            rmin = fminf(rmin, __shfl_xor_sync(0xffffffffu, rmin, 2));
            if (tg == 0) {
                int grow = rowi0 + li;
                atomicMax(&g_pos[grow], f2ord(rmax));
                atomicMin(&g_neg[grow], f2ord(rmin));
            }
        }

    // column-side reduction (always; symmetric dist values are idempotent)
#pragma unroll
    for (int s = 0; s < 16; s++) {
        float m_ = cmx[s], n_ = cmn[s];
        m_ = fmaxf(m_, __shfl_xor_sync(0xffffffffu, m_, 4));
        m_ = fmaxf(m_, __shfl_xor_sync(0xffffffffu, m_, 8));
        m_ = fmaxf(m_, __shfl_xor_sync(0xffffffffu, m_, 16));
        n_ = fminf(n_, __shfl_xor_sync(0xffffffffu, n_, 4));
        n_ = fminf(n_, __shfl_xor_sync(0xffffffffu, n_, 8));
        n_ = fminf(n_, __shfl_xor_sync(0xffffffffu, n_, 16));
        if (g == 0) {
            int gcol = rowj0 + wn * 64 + (s >> 1) * 8 + tg * 2 + (s & 1);
            atomicMax(&g_pos[gcol], f2ord(m_));
            atomicMin(&g_neg[gcol], f2ord(n_));
        }
    }

    // ---------------- last-block finalize (deterministic) -------------------
    __shared__ unsigned s_last;
    __threadfence();
    __syncthreads();
    if (tid == 0)
        s_last = (atomicAdd(&g_done, 1u) == (unsigned)(NTILES - 1));
    __syncthreads();
    if (s_last) {
        float ts = 0.f, cs = 0.f;
        for (int i = tid; i < N_ROWS; i += 256) {
            float p = ord2f(__ldcg(&g_pos[i]));
            float n = ord2f(__ldcg(&g_neg[i]));
            ts += fmaxf(p - n + MARGIN, 0.0f);
            cs += __ldcg(&g_ce[i]);
        }
#pragma unroll
        for (int o = 16; o; o >>= 1) {
            ts += __shfl_xor_sync(0xffffffffu, ts, o);
            cs += __shfl_xor_sync(0xffffffffu, cs, o);
        }
        if (lane == 0) { shw[warp] = ts; shw[8 + warp] = cs; }
        __syncthreads();
        if (tid == 0) {
            float tt = 0.f, ct = 0.f;
#pragma unroll
            for (int w = 0; w < 8; w++) { tt += shw[w]; ct += shw[8 + w]; }
            out[0] = tt / (float)N_ROWS + ct / (float)N_ROWS;
            g_done = 0;
            __threadfence();
        }
    }
}

// ---------------- entry -----------------------------------------------------
extern "C" void kernel_launch(void* const* d_in, const int* in_sizes, int n_in,
                              void* d_out, int out_size) {
    const float* x   = (const float*)d_in[0];
    const void*  lab = d_in[1];

    cudaFuncSetAttribute(gemm_kernel, cudaFuncAttributeMaxDynamicSharedMemorySize, SMEMDYN);
    prep_kernel<<<N_ROWS, 128>>>(x, lab);
    gemm_kernel<<<NTILES, 256, SMEMDYN>>>((float*)d_out);
}

// round 14
// speedup vs baseline: 2.5204x; 1.0265x over previous
#include <cuda_runtime.h>
#include <cuda_fp16.h>
#include <cstdint>

#define N_ROWS 8192
#define DIM    512
#define MARGIN 0.35f
#define KC     64                    // K elems per smem chunk (128B rows)
#define NCH    (DIM / KC)            // 8
#define TM     128                   // CTA tile rows (A)
#define TN     256                   // CTA tile cols (B)
#define ATILEB (TM * KC * 2)         // 16384
#define BTILEB (TN * KC * 2)         // 32768
#define STAGEB (ATILEB + BTILEB)     // 49152
#define SMEMDYN (2 * STAGEB)         // 98304 (double buffer)
#define NTILES 1056                  // {(bi,bj): 0<=bi<64, floor(bi/2)<=bj<32}

// ---------------- scratch (device globals; no allocation allowed) ----------
__device__ __align__(16) __half g_h[N_ROWS * DIM];
__device__ float    g_sq[N_ROWS];
__device__ float    g_ce[N_ROWS];
__device__ unsigned g_pos[N_ROWS];
__device__ unsigned g_neg[N_ROWS];
__device__ int      g_lab[N_ROWS];
__device__ unsigned g_done;          // zero-init; finalizer re-zeros for graph replay

// ---------------- float <-> monotone unsigned encoding ---------------------
__device__ __forceinline__ unsigned f2ord(float f) {
    unsigned u = __float_as_uint(f);
    return (u & 0x80000000u) ? ~u : (u | 0x80000000u);
}
__device__ __forceinline__ float ord2f(unsigned u) {
    unsigned b = (u & 0x80000000u) ? (u ^ 0x80000000u) : ~u;
    return __uint_as_float(b);
}
__device__ __forceinline__ float dev_inf() { return __int_as_float(0x7f800000); }

// ---------------- mbarrier helpers ------------------------------------------
#define MBAR_INIT(a, c) \
    asm volatile("mbarrier.init.shared.b64 [%0], %1;" :: "r"((uint32_t)(a)), "r"((uint32_t)(c)) : "memory")
#define MBAR_ARRIVE(a) \
    asm volatile("mbarrier.arrive.shared.b64 _, [%0];" :: "r"((uint32_t)(a)) : "memory")
#define CP_MBAR_ARRIVE(a) \
    asm volatile("cp.async.mbarrier.arrive.noinc.shared.b64 [%0];" :: "r"((uint32_t)(a)) : "memory")
#define MBAR_WAIT(a, ph) do {                                                          \
    uint32_t _m = (uint32_t)(a), _p = (uint32_t)(ph), _d;                              \
    asm volatile("{ .reg .pred p; mbarrier.try_wait.parity.acquire.cta.shared::cta.b64 p, [%1], %2;" \
                 " selp.b32 %0, 1, 0, p; }" : "=r"(_d) : "r"(_m), "r"(_p) : "memory"); \
    if (!_d) {                                                                         \
        asm volatile("{ .reg .pred P1; WL_%=: mbarrier.try_wait.parity.acquire.cta.shared::cta.b64 P1, [%0], %1, 0x989680;" \
                     " @P1 bra.uni WD_%=; bra.uni WL_%=; WD_%=: }" :: "r"(_m), "r"(_p) : "memory"); \
    } } while (0)
// relaxed: only for producer waits whose post-wait accesses are async-proxy (cp.async)
#define MBAR_WAIT_RELAXED(a, ph) do {                                                  \
    uint32_t _m = (uint32_t)(a), _p = (uint32_t)(ph), _d;                              \
    asm volatile("{ .reg .pred p; mbarrier.try_wait.parity.relaxed.cta.shared::cta.b64 p, [%1], %2, 0x989680;" \
                 " selp.b32 %0, 1, 0, p; }" : "=r"(_d) : "r"(_m), "r"(_p) : "memory"); \
    if (!_d) {                                                                         \
        asm volatile("{ .reg .pred P1; WL_%=: mbarrier.try_wait.parity.relaxed.cta.shared::cta.b64 P1, [%0], %1, 0x989680;" \
                     " @P1 bra.uni WD_%=; bra.uni WL_%=; WD_%=: }" :: "r"(_m), "r"(_p) : "memory"); \
    } } while (0)

// ---------------- prep: warp-per-row; norms, CE, fp16 cast, init ------------
__global__ void __launch_bounds__(256) prep_kernel(const float* __restrict__ x,
                                                   const void* __restrict__ labraw) {
    const int warp = threadIdx.x >> 5, lane = threadIdx.x & 31;
    const int row  = blockIdx.x * 8 + warp;
    const float* xr = x + (size_t)row * DIM;

    // label width: int64 labels in [0,512) -> odd 32-bit words all zero.
    const int* raw32 = (const int*)labraw;
    int lab64 = !__any_sync(0xffffffffu, raw32[2 * lane + 1] != 0);

    float v[16];
#pragma unroll
    for (int j = 0; j < 4; j++) {
        float4 f = *reinterpret_cast<const float4*>(xr + lane * 4 + 128 * j);
        v[j * 4 + 0] = f.x; v[j * 4 + 1] = f.y; v[j * 4 + 2] = f.z; v[j * 4 + 3] = f.w;
    }

    float ss = 0.f, mx = -dev_inf();
#pragma unroll
    for (int i = 0; i < 16; i++) { ss += v[i] * v[i]; mx = fmaxf(mx, v[i]); }
#pragma unroll
    for (int o = 16; o; o >>= 1) {
        ss += __shfl_xor_sync(0xffffffffu, ss, o);
        mx  = fmaxf(mx, __shfl_xor_sync(0xffffffffu, mx, o));
    }

    float norm = sqrtf(ss);
    float sq = 0.f, se = 0.f;
#pragma unroll
    for (int i = 0; i < 16; i++) {
        float xn = v[i] / norm;
        sq += xn * xn;
        se += expf(v[i] - mx);
    }
#pragma unroll
    for (int o = 16; o; o >>= 1) {
        sq += __shfl_xor_sync(0xffffffffu, sq, o);
        se += __shfl_xor_sync(0xffffffffu, se, o);
    }

    if (lane == 0) {
        int lb = lab64 ? (int)((const long long*)labraw)[row]
                       : ((const int*)labraw)[row];
        g_sq[row]  = sq;
        g_ce[row]  = mx + logf(se) - xr[lb];
        g_lab[row] = lb;
        g_pos[row] = f2ord(-dev_inf());
        g_neg[row] = f2ord(dev_inf());
    }

#pragma unroll
    for (int j = 0; j < 4; j++) {
        __half2 h0 = __floats2half2_rn(v[j * 4 + 0], v[j * 4 + 1]);
        __half2 h1 = __floats2half2_rn(v[j * 4 + 2], v[j * 4 + 3]);
        uint2 pk = make_uint2(*(uint32_t*)&h0, *(uint32_t*)&h1);
        *reinterpret_cast<uint2*>(g_h + (size_t)row * DIM + lane * 4 + 128 * j) = pk;
    }
}

// ---------------- mma helpers ----------------------------------------------
__device__ __forceinline__ void ldm_x4(uint32_t* d, uint32_t addr) {
    asm volatile("ldmatrix.sync.aligned.m8n8.x4.shared.b16 {%0,%1,%2,%3}, [%4];\n"
                 : "=r"(d[0]), "=r"(d[1]), "=r"(d[2]), "=r"(d[3]) : "r"(addr));
}
// fp16 accumulators: C fragment packed half2 x2
__device__ __forceinline__ void mma16816h(uint32_t* c, const uint32_t* a, const uint32_t* b) {
    asm volatile(
        "mma.sync.aligned.m16n8k16.row.col.f16.f16.f16.f16 "
        "{%0,%1}, {%2,%3,%4,%5}, {%6,%7}, {%0,%1};\n"
        : "+r"(c[0]), "+r"(c[1])
        : "r"(a[0]), "r"(a[1]), "r"(a[2]), "r"(a[3]), "r"(b[0]), "r"(b[1]));
}
__device__ __forceinline__ void cpasync16(uint32_t dst, const void* src) {
    asm volatile("cp.async.cg.shared.global [%0], [%1], 16;" :: "r"(dst), "l"(src));
}

// swizzled 16B-chunk byte offset for (row r, logical chunk c), 128B rows
__device__ __forceinline__ uint32_t swz8(int r, int c) {
    return (uint32_t)((r * 8 + (c ^ (r & 7))) << 4);
}

// ---------------- fused triangular GEMM + masked max/min + finalize --------
__global__ void __launch_bounds__(256, 2) gemm_kernel(float* out) {
    extern __shared__ __align__(1024) char smdyn[];
    __shared__ __align__(8) unsigned long long s_mbar[4]; // full[2], empty[2]
    __shared__ float s_sqi[TM], s_sqj[TN];
    __shared__ int   s_li[TM], s_lj[TN];
    __shared__ float shw[16];

    // map linear block -> tile (bi in 128-row units, bj in 256-col units, bj >= bi/2)
    int b = blockIdx.x;
    int bi = 0;
    for (;;) {
        int t = bi + 1, m = t >> 1;
        int cumn = (t & 1) ? (64 * m + 32 - m * m) : (64 * m - m * (m - 1));
        if (cumn > b) break;
        bi++;
    }
    int m0 = bi >> 1;
    int cumb = (bi & 1) ? (64 * m0 + 32 - m0 * m0) : (64 * m0 - m0 * (m0 - 1));
    int bj = (bi >> 1) + (b - cumb);

    const int tid  = threadIdx.x;
    const int lane = tid & 31, warp = tid >> 5;
    const int wm = warp & 1, wn = warp >> 1;   // 2x4 warp grid: 64-row x 64-col per warp

    const int rowi0 = bi * TM, rowj0 = bj * TN;

    uint32_t smem0, mbar0;
    asm("{ .reg .u64 t; cvta.to.shared.u64 t, %1; cvt.u32.u64 %0, t; }"
        : "=r"(smem0) : "l"(smdyn));
    asm("{ .reg .u64 t; cvta.to.shared.u64 t, %1; cvt.u32.u64 %0, t; }"
        : "=r"(mbar0) : "l"(s_mbar));
    // full[s] = mbar0 + s*8 ; empty[s] = mbar0 + 16 + s*8

    if (tid == 0) {
#pragma unroll
        for (int s = 0; s < 2; s++) {
            MBAR_INIT(mbar0 + s * 8, 256);        // full: 256 cp-async arrives
            MBAR_INIT(mbar0 + 16 + s * 8, 256);   // empty: 256 thread arrives
        }
    }
    if (tid < TM) { s_sqi[tid] = g_sq[rowi0 + tid]; s_li[tid] = g_lab[rowi0 + tid]; }
    s_sqj[tid] = g_sq[rowj0 + tid];
    s_lj[tid]  = g_lab[rowj0 + tid];
    __syncthreads();                              // mbarriers + metadata visible

    auto issue_chunk = [&](int k, int stage) {
        const int kt = k * KC;
        const uint32_t sbA = smem0 + stage * STAGEB;
        const uint32_t sbB = sbA + ATILEB;
#pragma unroll
        for (int rep = 0; rep < 4; rep++) {           // A: 128 rows x 8 chunks
            int q = rep * 256 + tid;
            int r = q >> 3, c = q & 7;
            cpasync16(sbA + swz8(r, c), g_h + (size_t)(rowi0 + r) * DIM + kt + c * 8);
        }
#pragma unroll
        for (int rep = 0; rep < 8; rep++) {           // B: 256 rows x 8 chunks
            int q = rep * 256 + tid;
            int r = q >> 3, c = q & 7;
            cpasync16(sbB + swz8(r, c), g_h + (size_t)(rowj0 + r) * DIM + kt + c * 8);
        }
        CP_MBAR_ARRIVE(mbar0 + stage * 8);
    };

    issue_chunk(0, 0);
    issue_chunk(1, 1);

    uint32_t acc[4][8][2];
#pragma unroll
    for (int mi = 0; mi < 4; mi++)
#pragma unroll
        for (int ni = 0; ni < 8; ni++) { acc[mi][ni][0] = 0u; acc[mi][ni][1] = 0u; }

    const int m4 = lane >> 3, ri = lane & 7;

    for (int k = 0; k < NCH; k++) {
        const int st = k & 1;
        const int ph = (k >> 1) & 1;
        MBAR_WAIT(mbar0 + st * 8, ph);            // chunk k data ready

        const uint32_t baseA = smem0 + st * STAGEB;
        const uint32_t baseB = baseA + ATILEB;

#pragma unroll
        for (int kk = 0; kk < 3; kk++) {
            uint32_t ah[4][4];
#pragma unroll
            for (int mi = 0; mi < 4; mi++) {
                int r = wm * 64 + mi * 16 + (m4 & 1) * 8 + ri;
                int c = kk * 2 + (m4 >> 1);
                ldm_x4(ah[mi], baseA + swz8(r, c));
            }
            uint32_t bh[4][4];
#pragma unroll
            for (int p4 = 0; p4 < 4; p4++) {
                int r = wn * 64 + p4 * 16 + (m4 >> 1) * 8 + ri;
                int c = kk * 2 + (m4 & 1);
                ldm_x4(bh[p4], baseB + swz8(r, c));
            }
#pragma unroll
            for (int mi = 0; mi < 4; mi++)
#pragma unroll
                for (int ni = 0; ni < 8; ni++)
                    mma16816h(acc[mi][ni], ah[mi], &bh[ni >> 1][(ni & 1) * 2]);
        }
        {   // kk = 3: load fragments, release stage EARLY, then compute
            uint32_t ah[4][4];
#pragma unroll
            for (int mi = 0; mi < 4; mi++) {
                int r = wm * 64 + mi * 16 + (m4 & 1) * 8 + ri;
                int c = 6 + (m4 >> 1);
                ldm_x4(ah[mi], baseA + swz8(r, c));
            }
            uint32_t bh[4][4];
#pragma unroll
            for (int p4 = 0; p4 < 4; p4++) {
                int r = wn * 64 + p4 * 16 + (m4 >> 1) * 8 + ri;
                int c = 6 + (m4 & 1);
                ldm_x4(bh[p4], baseB + swz8(r, c));
            }
            MBAR_ARRIVE(mbar0 + 16 + st * 8);     // stage reads complete (regs hold data)
#pragma unroll
            for (int mi = 0; mi < 4; mi++)
#pragma unroll
                for (int ni = 0; ni < 8; ni++)
                    mma16816h(acc[mi][ni], ah[mi], &bh[ni >> 1][(ni & 1) * 2]);
        }

        if (k + 2 < NCH) {
            MBAR_WAIT_RELAXED(mbar0 + 16 + st * 8, ph);  // all warps' LDSMs done
            issue_chunk(k + 2, st);
        }
    }

    // ---------------- epilogue: dist + masked max/min reductions -----------
    const int g = lane >> 2, tg = lane & 3;
    const float NEG = -dev_inf(), POS = dev_inf();
    float cmx[16], cmn[16];
#pragma unroll
    for (int s = 0; s < 16; s++) { cmx[s] = NEG; cmn[s] = POS; }

#pragma unroll
    for (int mi = 0; mi < 4; mi++)
#pragma unroll
        for (int h = 0; h < 2; h++) {
            int li = wm * 64 + mi * 16 + h * 8 + g;
            int labi = s_li[li];
            float sqi = s_sqi[li];
            float rmax = NEG, rmin = POS;
#pragma unroll
            for (int ni = 0; ni < 8; ni++) {
                float2 f = __half22float2(*reinterpret_cast<__half2*>(&acc[mi][ni][h]));
#pragma unroll
                for (int cc = 0; cc < 2; cc++) {
                    int lj = wn * 64 + ni * 8 + tg * 2 + cc;
                    float d = sqi + s_sqj[lj] - 2.0f * (cc ? f.y : f.x);
                    int s = ni * 2 + cc;
                    if (labi == s_lj[lj]) {
                        rmax = fmaxf(rmax, d);
                        cmx[s] = fmaxf(cmx[s], d);
                    } else {
                        rmin = fminf(rmin, d);
                        cmn[s] = fminf(cmn[s], d);
                    }
                }
            }
            // row reduction across tg (low 2 lane bits)
            rmax = fmaxf(rmax, __shfl_xor_sync(0xffffffffu, rmax, 1));
            rmax = fmaxf(rmax, __shfl_xor_sync(0xffffffffu, rmax, 2));
            rmin = fminf(rmin, __shfl_xor_sync(0xffffffffu, rmin, 1));
            rmin = fminf(rmin, __shfl_xor_sync(0xffffffffu, rmin, 2));
            if (tg == 0) {
                int grow = rowi0 + li;
                atomicMax(&g_pos[grow], f2ord(rmax));
                atomicMin(&g_neg[grow], f2ord(rmin));
            }
        }

    // column-side reduction (always; symmetric dist values are idempotent)
#pragma unroll
    for (int s = 0; s < 16; s++) {
        float m_ = cmx[s], n_ = cmn[s];
        m_ = fmaxf(m_, __shfl_xor_sync(0xffffffffu, m_, 4));
        m_ = fmaxf(m_, __shfl_xor_sync(0xffffffffu, m_, 8));
        m_ = fmaxf(m_, __shfl_xor_sync(0xffffffffu, m_, 16));
        n_ = fminf(n_, __shfl_xor_sync(0xffffffffu, n_, 4));
        n_ = fminf(n_, __shfl_xor_sync(0xffffffffu, n_, 8));
        n_ = fminf(n_, __shfl_xor_sync(0xffffffffu, n_, 16));
        if (g == 0) {
            int gcol = rowj0 + wn * 64 + (s >> 1) * 8 + tg * 2 + (s & 1);
            atomicMax(&g_pos[gcol], f2ord(m_));
            atomicMin(&g_neg[gcol], f2ord(n_));
        }
    }

    // ---------------- last-block finalize (deterministic) -------------------
    __shared__ unsigned s_last;
    __threadfence();
    __syncthreads();
    if (tid == 0)
        s_last = (atomicAdd(&g_done, 1u) == (unsigned)(NTILES - 1));
    __syncthreads();
    if (s_last) {
        float ts = 0.f, cs = 0.f;
        for (int i = tid; i < N_ROWS; i += 256) {
            float p = ord2f(__ldcg(&g_pos[i]));
            float n = ord2f(__ldcg(&g_neg[i]));
            ts += fmaxf(p - n + MARGIN, 0.0f);
            cs += __ldcg(&g_ce[i]);
        }
#pragma unroll
        for (int o = 16; o; o >>= 1) {
            ts += __shfl_xor_sync(0xffffffffu, ts, o);
            cs += __shfl_xor_sync(0xffffffffu, cs, o);
        }
        if (lane == 0) { shw[warp] = ts; shw[8 + warp] = cs; }
        __syncthreads();
        if (tid == 0) {
            float tt = 0.f, ct = 0.f;
#pragma unroll
            for (int w = 0; w < 8; w++) { tt += shw[w]; ct += shw[8 + w]; }
            out[0] = tt / (float)N_ROWS + ct / (float)N_ROWS;
            g_done = 0;
            __threadfence();
        }
    }
}

// ---------------- entry -----------------------------------------------------
extern "C" void kernel_launch(void* const* d_in, const int* in_sizes, int n_in,
                              void* d_out, int out_size) {
    const float* x   = (const float*)d_in[0];
    const void*  lab = d_in[1];

    cudaFuncSetAttribute(gemm_kernel, cudaFuncAttributeMaxDynamicSharedMemorySize, SMEMDYN);
    prep_kernel<<<N_ROWS / 8, 256>>>(x, lab);
    gemm_kernel<<<NTILES, 256, SMEMDYN>>>((float*)d_out);
}

// round 15
// speedup vs baseline: 2.6143x; 1.0372x over previous
#include <cuda_runtime.h>
#include <cuda_fp16.h>
#include <cstdint>

#define N_ROWS 8192
#define DIM    512
#define MARGIN 0.35f
#define KC     64                    // K elems per smem chunk (128B rows)
#define NCH    (DIM / KC)            // 8
#define TM     128                   // CTA tile rows (A)
#define TN     256                   // CTA tile cols (B)
#define ATILEB (TM * KC * 2)         // 16384
#define BTILEB (TN * KC * 2)         // 32768
#define STAGEB (ATILEB + BTILEB)     // 49152
#define SMEMDYN (2 * STAGEB)         // 98304 (double buffer)
#define NTILES 1056                  // {(bi,bj): 0<=bi<64, floor(bi/2)<=bj<32}

// ---------------- scratch (device globals; no allocation allowed) ----------
__device__ __align__(16) __half g_h[N_ROWS * DIM];
__device__ float    g_sq[N_ROWS];
__device__ float    g_ce[N_ROWS];
__device__ unsigned g_pos[N_ROWS];
__device__ unsigned g_neg[N_ROWS];
__device__ int      g_lab[N_ROWS];
__device__ unsigned g_done;          // zero-init; finalizer re-zeros for graph replay

// ---------------- float <-> monotone unsigned encoding ---------------------
__device__ __forceinline__ unsigned f2ord(float f) {
    unsigned u = __float_as_uint(f);
    return (u & 0x80000000u) ? ~u : (u | 0x80000000u);
}
__device__ __forceinline__ float ord2f(unsigned u) {
    unsigned b = (u & 0x80000000u) ? (u ^ 0x80000000u) : ~u;
    return __uint_as_float(b);
}
__device__ __forceinline__ float dev_inf() { return __int_as_float(0x7f800000); }

// ---------------- mbarrier helpers ------------------------------------------
#define MBAR_INIT(a, c) \
    asm volatile("mbarrier.init.shared.b64 [%0], %1;" :: "r"((uint32_t)(a)), "r"((uint32_t)(c)) : "memory")
#define MBAR_ARRIVE(a) \
    asm volatile("mbarrier.arrive.shared.b64 _, [%0];" :: "r"((uint32_t)(a)) : "memory")
#define CP_MBAR_ARRIVE(a) \
    asm volatile("cp.async.mbarrier.arrive.noinc.shared.b64 [%0];" :: "r"((uint32_t)(a)) : "memory")
#define MBAR_WAIT(a, ph) do {                                                          \
    uint32_t _m = (uint32_t)(a), _p = (uint32_t)(ph), _d;                              \
    asm volatile("{ .reg .pred p; mbarrier.try_wait.parity.acquire.cta.shared::cta.b64 p, [%1], %2;" \
                 " selp.b32 %0, 1, 0, p; }" : "=r"(_d) : "r"(_m), "r"(_p) : "memory"); \
    if (!_d) {                                                                         \
        asm volatile("{ .reg .pred P1; WL_%=: mbarrier.try_wait.parity.acquire.cta.shared::cta.b64 P1, [%0], %1, 0x989680;" \
                     " @P1 bra.uni WD_%=; bra.uni WL_%=; WD_%=: }" :: "r"(_m), "r"(_p) : "memory"); \
    } } while (0)
// relaxed: only for producer waits whose post-wait accesses are async-proxy (cp.async)
#define MBAR_WAIT_RELAXED(a, ph) do {                                                  \
    uint32_t _m = (uint32_t)(a), _p = (uint32_t)(ph), _d;                              \
    asm volatile("{ .reg .pred p; mbarrier.try_wait.parity.relaxed.cta.shared::cta.b64 p, [%1], %2, 0x989680;" \
                 " selp.b32 %0, 1, 0, p; }" : "=r"(_d) : "r"(_m), "r"(_p) : "memory"); \
    if (!_d) {                                                                         \
        asm volatile("{ .reg .pred P1; WL_%=: mbarrier.try_wait.parity.relaxed.cta.shared::cta.b64 P1, [%0], %1, 0x989680;" \
                     " @P1 bra.uni WD_%=; bra.uni WL_%=; WD_%=: }" :: "r"(_m), "r"(_p) : "memory"); \
    } } while (0)

// ---------------- prep: warp-per-row; norms, CE, fp16 cast, init ------------
__global__ void __launch_bounds__(256) prep_kernel(const float* __restrict__ x,
                                                   const void* __restrict__ labraw) {
    const int warp = threadIdx.x >> 5, lane = threadIdx.x & 31;
    const int row  = blockIdx.x * 8 + warp;
    const float* xr = x + (size_t)row * DIM;

    // label width: int64 labels in [0,512) -> odd 32-bit words all zero.
    const int* raw32 = (const int*)labraw;
    int lab64 = !__any_sync(0xffffffffu, raw32[2 * lane + 1] != 0);

    float v[16];
#pragma unroll
    for (int j = 0; j < 4; j++) {
        float4 f = *reinterpret_cast<const float4*>(xr + lane * 4 + 128 * j);
        v[j * 4 + 0] = f.x; v[j * 4 + 1] = f.y; v[j * 4 + 2] = f.z; v[j * 4 + 3] = f.w;
    }

    float ss = 0.f, mx = -dev_inf();
#pragma unroll
    for (int i = 0; i < 16; i++) { ss += v[i] * v[i]; mx = fmaxf(mx, v[i]); }
#pragma unroll
    for (int o = 16; o; o >>= 1) {
        ss += __shfl_xor_sync(0xffffffffu, ss, o);
        mx  = fmaxf(mx, __shfl_xor_sync(0xffffffffu, mx, o));
    }

    float norm = sqrtf(ss);
    float sq = 0.f, se = 0.f;
#pragma unroll
    for (int i = 0; i < 16; i++) {
        float xn = v[i] / norm;
        sq += xn * xn;
        se += expf(v[i] - mx);
    }
#pragma unroll
    for (int o = 16; o; o >>= 1) {
        sq += __shfl_xor_sync(0xffffffffu, sq, o);
        se += __shfl_xor_sync(0xffffffffu, se, o);
    }

    if (lane == 0) {
        int lb = lab64 ? (int)((const long long*)labraw)[row]
                       : ((const int*)labraw)[row];
        g_sq[row]  = sq;
        g_ce[row]  = mx + logf(se) - xr[lb];
        g_lab[row] = lb;
        g_pos[row] = f2ord(-dev_inf());
        g_neg[row] = f2ord(dev_inf());
    }

#pragma unroll
    for (int j = 0; j < 4; j++) {
        __half2 h0 = __floats2half2_rn(v[j * 4 + 0], v[j * 4 + 1]);
        __half2 h1 = __floats2half2_rn(v[j * 4 + 2], v[j * 4 + 3]);
        uint2 pk = make_uint2(*(uint32_t*)&h0, *(uint32_t*)&h1);
        *reinterpret_cast<uint2*>(g_h + (size_t)row * DIM + lane * 4 + 128 * j) = pk;
    }
}

// ---------------- mma helpers ----------------------------------------------
__device__ __forceinline__ void ldm_x4(uint32_t* d, uint32_t addr) {
    asm volatile("ldmatrix.sync.aligned.m8n8.x4.shared.b16 {%0,%1,%2,%3}, [%4];\n"
                 : "=r"(d[0]), "=r"(d[1]), "=r"(d[2]), "=r"(d[3]) : "r"(addr));
}
// fp16 accumulators: C fragment packed half2 x2
__device__ __forceinline__ void mma16816h(uint32_t* c, const uint32_t* a, const uint32_t* b) {
    asm volatile(
        "mma.sync.aligned.m16n8k16.row.col.f16.f16.f16.f16 "
        "{%0,%1}, {%2,%3,%4,%5}, {%6,%7}, {%0,%1};\n"
        : "+r"(c[0]), "+r"(c[1])
        : "r"(a[0]), "r"(a[1]), "r"(a[2]), "r"(a[3]), "r"(b[0]), "r"(b[1]));
}
__device__ __forceinline__ void cpasync16(uint32_t dst, const void* src) {
    asm volatile("cp.async.cg.shared.global [%0], [%1], 16;" :: "r"(dst), "l"(src));
}

// swizzled 16B-chunk byte offset for (row r, logical chunk c), 128B rows
__device__ __forceinline__ uint32_t swz8(int r, int c) {
    return (uint32_t)((r * 8 + (c ^ (r & 7))) << 4);
}

// ---------------- fused triangular GEMM + masked max/min + finalize --------
__global__ void __launch_bounds__(256, 2) gemm_kernel(float* out) {
    extern __shared__ __align__(1024) char smdyn[];
    __shared__ __align__(8) unsigned long long s_mbar[4]; // full[2], empty[2]
    __shared__ float s_sqi[TM], s_sqj[TN];
    __shared__ int   s_li[TM], s_lj[TN];
    __shared__ float shw[16];

    // map linear block -> tile (bi in 128-row units, bj in 256-col units, bj >= bi/2)
    int b = blockIdx.x;
    int bi = 0;
    for (;;) {
        int t = bi + 1, m = t >> 1;
        int cumn = (t & 1) ? (64 * m + 32 - m * m) : (64 * m - m * (m - 1));
        if (cumn > b) break;
        bi++;
    }
    int m0 = bi >> 1;
    int cumb = (bi & 1) ? (64 * m0 + 32 - m0 * m0) : (64 * m0 - m0 * (m0 - 1));
    int bj = (bi >> 1) + (b - cumb);

    const int tid  = threadIdx.x;
    const int lane = tid & 31, warp = tid >> 5;
    const int wm = warp & 1, wn = warp >> 1;   // 2x4 warp grid: 64-row x 64-col per warp

    const int rowi0 = bi * TM, rowj0 = bj * TN;

    uint32_t smem0, mbar0;
    asm("{ .reg .u64 t; cvta.to.shared.u64 t, %1; cvt.u32.u64 %0, t; }"
        : "=r"(smem0) : "l"(smdyn));
    asm("{ .reg .u64 t; cvta.to.shared.u64 t, %1; cvt.u32.u64 %0, t; }"
        : "=r"(mbar0) : "l"(s_mbar));
    // full[s] = mbar0 + s*8 ; empty[s] = mbar0 + 16 + s*8

    if (tid == 0) {
#pragma unroll
        for (int s = 0; s < 2; s++) {
            MBAR_INIT(mbar0 + s * 8, 256);        // full: 256 cp-async arrives
            MBAR_INIT(mbar0 + 16 + s * 8, 8);     // empty: 8 warp-elected arrives
        }
    }
    if (tid < TM) { s_sqi[tid] = g_sq[rowi0 + tid]; s_li[tid] = g_lab[rowi0 + tid]; }
    s_sqj[tid] = g_sq[rowj0 + tid];
    s_lj[tid]  = g_lab[rowj0 + tid];
    __syncthreads();                              // mbarriers + metadata visible

    auto issue_chunk = [&](int k, int stage) {
        const int kt = k * KC;
        const uint32_t sbA = smem0 + stage * STAGEB;
        const uint32_t sbB = sbA + ATILEB;
#pragma unroll
        for (int rep = 0; rep < 4; rep++) {           // A: 128 rows x 8 chunks
            int q = rep * 256 + tid;
            int r = q >> 3, c = q & 7;
            cpasync16(sbA + swz8(r, c), g_h + (size_t)(rowi0 + r) * DIM + kt + c * 8);
        }
#pragma unroll
        for (int rep = 0; rep < 8; rep++) {           // B: 256 rows x 8 chunks
            int q = rep * 256 + tid;
            int r = q >> 3, c = q & 7;
            cpasync16(sbB + swz8(r, c), g_h + (size_t)(rowj0 + r) * DIM + kt + c * 8);
        }
        CP_MBAR_ARRIVE(mbar0 + stage * 8);
    };

    issue_chunk(0, 0);
    issue_chunk(1, 1);

    uint32_t acc[4][8][2];
#pragma unroll
    for (int mi = 0; mi < 4; mi++)
#pragma unroll
        for (int ni = 0; ni < 8; ni++) { acc[mi][ni][0] = 0u; acc[mi][ni][1] = 0u; }

    const int m4 = lane >> 3, ri = lane & 7;

#pragma unroll
    for (int k = 0; k < NCH; k++) {               // FULL UNROLL: st/ph/bases constant
        const int st = k & 1;
        const int ph = (k >> 1) & 1;
        MBAR_WAIT(mbar0 + st * 8, ph);            // chunk k data ready

        const uint32_t baseA = smem0 + st * STAGEB;
        const uint32_t baseB = baseA + ATILEB;

#pragma unroll
        for (int kk = 0; kk < 3; kk++) {
            uint32_t ah[4][4];
#pragma unroll
            for (int mi = 0; mi < 4; mi++) {
                int r = wm * 64 + mi * 16 + (m4 & 1) * 8 + ri;
                int c = kk * 2 + (m4 >> 1);
                ldm_x4(ah[mi], baseA + swz8(r, c));
            }
            uint32_t bh[4][4];
#pragma unroll
            for (int p4 = 0; p4 < 4; p4++) {
                int r = wn * 64 + p4 * 16 + (m4 >> 1) * 8 + ri;
                int c = kk * 2 + (m4 & 1);
                ldm_x4(bh[p4], baseB + swz8(r, c));
            }
#pragma unroll
            for (int mi = 0; mi < 4; mi++)
#pragma unroll
                for (int ni = 0; ni < 8; ni++)
                    mma16816h(acc[mi][ni], ah[mi], &bh[ni >> 1][(ni & 1) * 2]);
        }
        {   // kk = 3: load fragments, release stage EARLY (warp-elected), then compute
            uint32_t ah[4][4];
#pragma unroll
            for (int mi = 0; mi < 4; mi++) {
                int r = wm * 64 + mi * 16 + (m4 & 1) * 8 + ri;
                int c = 6 + (m4 >> 1);
                ldm_x4(ah[mi], baseA + swz8(r, c));
            }
            uint32_t bh[4][4];
#pragma unroll
            for (int p4 = 0; p4 < 4; p4++) {
                int r = wn * 64 + p4 * 16 + (m4 >> 1) * 8 + ri;
                int c = 6 + (m4 & 1);
                ldm_x4(bh[p4], baseB + swz8(r, c));
            }
            if (lane == 0) MBAR_ARRIVE(mbar0 + 16 + st * 8);  // warp's smem reads done
#pragma unroll
            for (int mi = 0; mi < 4; mi++)
#pragma unroll
                for (int ni = 0; ni < 8; ni++)
                    mma16816h(acc[mi][ni], ah[mi], &bh[ni >> 1][(ni & 1) * 2]);
        }

        if (k + 2 < NCH) {
            MBAR_WAIT_RELAXED(mbar0 + 16 + st * 8, ph);  // all 8 warps' LDSMs done
            issue_chunk(k + 2, st);
        }
    }

    // ---------------- epilogue: dist + masked max/min reductions -----------
    const int g = lane >> 2, tg = lane & 3;
    const float NEG = -dev_inf(), POS = dev_inf();
    float cmx[16], cmn[16];
#pragma unroll
    for (int s = 0; s < 16; s++) { cmx[s] = NEG; cmn[s] = POS; }

#pragma unroll
    for (int mi = 0; mi < 4; mi++)
#pragma unroll
        for (int h = 0; h < 2; h++) {
            int li = wm * 64 + mi * 16 + h * 8 + g;
            int labi = s_li[li];
            float sqi = s_sqi[li];
            float rmax = NEG, rmin = POS;
#pragma unroll
            for (int ni = 0; ni < 8; ni++) {
                float2 f = __half22float2(*reinterpret_cast<__half2*>(&acc[mi][ni][h]));
#pragma unroll
                for (int cc = 0; cc < 2; cc++) {
                    int lj = wn * 64 + ni * 8 + tg * 2 + cc;
                    float d = sqi + s_sqj[lj] - 2.0f * (cc ? f.y : f.x);
                    int s = ni * 2 + cc;
                    if (labi == s_lj[lj]) {
                        rmax = fmaxf(rmax, d);
                        cmx[s] = fmaxf(cmx[s], d);
                    } else {
                        rmin = fminf(rmin, d);
                        cmn[s] = fminf(cmn[s], d);
                    }
                }
            }
            // row reduction across tg (low 2 lane bits)
            rmax = fmaxf(rmax, __shfl_xor_sync(0xffffffffu, rmax, 1));
            rmax = fmaxf(rmax, __shfl_xor_sync(0xffffffffu, rmax, 2));
            rmin = fminf(rmin, __shfl_xor_sync(0xffffffffu, rmin, 1));
            rmin = fminf(rmin, __shfl_xor_sync(0xffffffffu, rmin, 2));
            if (tg == 0) {
                int grow = rowi0 + li;
                atomicMax(&g_pos[grow], f2ord(rmax));
                atomicMin(&g_neg[grow], f2ord(rmin));
            }
        }

    // column-side reduction (always; symmetric dist values are idempotent)
#pragma unroll
    for (int s = 0; s < 16; s++) {
        float m_ = cmx[s], n_ = cmn[s];
        m_ = fmaxf(m_, __shfl_xor_sync(0xffffffffu, m_, 4));
        m_ = fmaxf(m_, __shfl_xor_sync(0xffffffffu, m_, 8));
        m_ = fmaxf(m_, __shfl_xor_sync(0xffffffffu, m_, 16));
        n_ = fminf(n_, __shfl_xor_sync(0xffffffffu, n_, 4));
        n_ = fminf(n_, __shfl_xor_sync(0xffffffffu, n_, 8));
        n_ = fminf(n_, __shfl_xor_sync(0xffffffffu, n_, 16));
        if (g == 0) {
            int gcol = rowj0 + wn * 64 + (s >> 1) * 8 + tg * 2 + (s & 1);
            atomicMax(&g_pos[gcol], f2ord(m_));
            atomicMin(&g_neg[gcol], f2ord(n_));
        }
    }

    // ---------------- last-block finalize (deterministic) -------------------
    __shared__ unsigned s_last;
    __threadfence();
    __syncthreads();
    if (tid == 0)
        s_last = (atomicAdd(&g_done, 1u) == (unsigned)(NTILES - 1));
    __syncthreads();
    if (s_last) {
        float ts = 0.f, cs = 0.f;
        for (int i = tid; i < N_ROWS; i += 256) {
            float p = ord2f(__ldcg(&g_pos[i]));
            float n = ord2f(__ldcg(&g_neg[i]));
            ts += fmaxf(p - n + MARGIN, 0.0f);
            cs += __ldcg(&g_ce[i]);
        }
#pragma unroll
        for (int o = 16; o; o >>= 1) {
            ts += __shfl_xor_sync(0xffffffffu, ts, o);
            cs += __shfl_xor_sync(0xffffffffu, cs, o);
        }
        if (lane == 0) { shw[warp] = ts; shw[8 + warp] = cs; }
        __syncthreads();
        if (tid == 0) {
            float tt = 0.f, ct = 0.f;
#pragma unroll
            for (int w = 0; w < 8; w++) { tt += shw[w]; ct += shw[8 + w]; }
            out[0] = tt / (float)N_ROWS + ct / (float)N_ROWS;
            g_done = 0;
            __threadfence();
        }
    }
}

// ---------------- entry -----------------------------------------------------
extern "C" void kernel_launch(void* const* d_in, const int* in_sizes, int n_in,
                              void* d_out, int out_size) {
    const float* x   = (const float*)d_in[0];
    const void*  lab = d_in[1];

    cudaFuncSetAttribute(gemm_kernel, cudaFuncAttributeMaxDynamicSharedMemorySize, SMEMDYN);
    prep_kernel<<<N_ROWS / 8, 256>>>(x, lab);
    gemm_kernel<<<NTILES, 256, SMEMDYN>>>((float*)d_out);
}